// round 1
// baseline (speedup 1.0000x reference)
#include <cuda_runtime.h>
#include <math.h>

// Problem constants
constexpr int S_   = 128;   // sequence length
constexpr int B_   = 64;    // batch
constexpr int E_   = 256;   // embedding dim
constexpr int H_   = 256;   // hidden
constexpr int G4_  = 1024;  // 4*H (gates)
constexpr int HID_ = 30;    // attention hidden

// Scratch (static device globals — no runtime allocation)
__device__ float g_emb[S_ * B_ * E_];        // (t,b,e)  8 MB
__device__ float g_X[2 * S_ * B_ * G4_];     // x-projections per dir, bias folded in (67 MB)
__device__ float g_h[2 * S_ * B_ * H_];      // fwd_out / bwd_rev_out  (t,b,h)
__device__ float g_c[2 * B_ * H_];           // cell state per dir
__device__ float g_U[B_ * S_ * HID_];        // u = enc @ Ua^T
__device__ float g_Wt[B_ * HID_ * S_];       // w transposed: [b][k][s]

__device__ __forceinline__ float sigmoidf_(float x) { return 1.0f / (1.0f + expf(-x)); }

// ---------------------------------------------------------------------------
// K1: embedding gather.  grid = S*B blocks, 64 threads (float4 row copy)
// ---------------------------------------------------------------------------
__global__ void k_gather(const int* __restrict__ concepts,
                         const float* __restrict__ table) {
    int tb  = blockIdx.x;                      // t*B + b
    int tok = concepts[tb];
    const float4* src = reinterpret_cast<const float4*>(table + (size_t)tok * E_);
    float4*       dst = reinterpret_cast<float4*>(g_emb + (size_t)tb * E_);
    dst[threadIdx.x] = src[threadIdx.x];
}

// ---------------------------------------------------------------------------
// K2: x-projection GEMM  X[dir] = emb @ Wih[dir]^T + b[dir]
//     M=8192, N=1024, K=256.  BM=BN=128, BK=16, 256 thr, 8x8 microtile.
// ---------------------------------------------------------------------------
__global__ __launch_bounds__(256) void k_xgemm(const float* __restrict__ Wih_f,
                                               const float* __restrict__ b_f,
                                               const float* __restrict__ Wih_b,
                                               const float* __restrict__ b_b) {
    const int dir = blockIdx.z;
    const float* __restrict__ Wih  = dir ? Wih_b : Wih_f;
    const float* __restrict__ bias = dir ? b_b   : b_f;
    float* __restrict__ Xout = g_X + (size_t)dir * S_ * B_ * G4_;

    __shared__ float As[16][132];   // [k][m] k-major
    __shared__ float Bs[16][132];   // [k][n]

    const int m0  = blockIdx.x * 128;
    const int n0  = blockIdx.y * 128;
    const int tid = threadIdx.x;
    const int tx  = tid & 15;       // -> n
    const int ty  = tid >> 4;       // -> m

    float acc[8][8];
#pragma unroll
    for (int i = 0; i < 8; i++)
#pragma unroll
        for (int j = 0; j < 8; j++) acc[i][j] = 0.0f;

    for (int kc = 0; kc < E_; kc += 16) {
#pragma unroll
        for (int p = 0; p < 2; p++) {
            int q  = tid + p * 256;        // 0..511 quads
            int r  = q >> 2;               // row 0..127
            int kq = (q & 3) * 4;          // k quad
            float4 va = *reinterpret_cast<const float4*>(g_emb + (size_t)(m0 + r) * E_ + kc + kq);
            As[kq + 0][r] = va.x; As[kq + 1][r] = va.y;
            As[kq + 2][r] = va.z; As[kq + 3][r] = va.w;
            float4 vb = *reinterpret_cast<const float4*>(Wih + (size_t)(n0 + r) * E_ + kc + kq);
            Bs[kq + 0][r] = vb.x; Bs[kq + 1][r] = vb.y;
            Bs[kq + 2][r] = vb.z; Bs[kq + 3][r] = vb.w;
        }
        __syncthreads();
#pragma unroll
        for (int k = 0; k < 16; k++) {
            float a[8], bb[8];
            *reinterpret_cast<float4*>(&a[0])  = *reinterpret_cast<const float4*>(&As[k][ty * 8]);
            *reinterpret_cast<float4*>(&a[4])  = *reinterpret_cast<const float4*>(&As[k][ty * 8 + 4]);
            *reinterpret_cast<float4*>(&bb[0]) = *reinterpret_cast<const float4*>(&Bs[k][tx * 8]);
            *reinterpret_cast<float4*>(&bb[4]) = *reinterpret_cast<const float4*>(&Bs[k][tx * 8 + 4]);
#pragma unroll
            for (int i = 0; i < 8; i++)
#pragma unroll
                for (int j = 0; j < 8; j++) acc[i][j] += a[i] * bb[j];
        }
        __syncthreads();
    }

    // epilogue: add bias, contiguous float4 stores
    float bv[8];
#pragma unroll
    for (int j = 0; j < 8; j++) bv[j] = bias[n0 + tx * 8 + j];
#pragma unroll
    for (int i = 0; i < 8; i++) {
        int m = m0 + ty * 8 + i;
        float4 o0, o1;
        o0.x = acc[i][0] + bv[0]; o0.y = acc[i][1] + bv[1];
        o0.z = acc[i][2] + bv[2]; o0.w = acc[i][3] + bv[3];
        o1.x = acc[i][4] + bv[4]; o1.y = acc[i][5] + bv[5];
        o1.z = acc[i][6] + bv[6]; o1.w = acc[i][7] + bv[7];
        float* dst = Xout + (size_t)m * G4_ + n0 + tx * 8;
        *reinterpret_cast<float4*>(dst)     = o0;
        *reinterpret_cast<float4*>(dst + 4) = o1;
    }
}

// ---------------------------------------------------------------------------
// K3: one LSTM time step, both directions (blockIdx.y = dir).
//     blockIdx.x in [0,64): owns 4 h-channels (x4 gates = 16 Whh rows)
//     for all 64 batch elements.  256 threads: (rr 0..15, 4 batches each).
//     Pointwise c/h update is block-local.
// ---------------------------------------------------------------------------
__global__ __launch_bounds__(256) void k_step(int t,
                                              const int* __restrict__ lens,
                                              const float* __restrict__ Whh_f,
                                              const float* __restrict__ Whh_b) {
    const int dir = blockIdx.y;
    const float* __restrict__ Whh = dir ? Whh_b : Whh_f;
    const float* __restrict__ X   = g_X + (size_t)dir * S_ * B_ * G4_;
    float* __restrict__ hout = g_h + (size_t)dir * S_ * B_ * H_;
    float* __restrict__ cst  = g_c + dir * B_ * H_;

    const int j0  = blockIdx.x * 4;          // channel base
    const int tid = threadIdx.x;
    const int rr  = tid & 15;                // which of 16 gate-rows
    const int bq  = tid >> 4;                // 0..15
    const int b0  = bq * 4;                  // batch base (4 per thread)
    const int row = (rr >> 2) * H_ + j0 + (rr & 3);   // Whh/gate row (i,f,g,o blocks)

    __shared__ float w_s[16][257];           // [rr][k]
    __shared__ float h_s[64][68];            // [k within chunk][b]
    __shared__ float gates_s[16][65];        // [rr][b]

    float acc0 = 0.f, acc1 = 0.f, acc2 = 0.f, acc3 = 0.f;

    if (t > 0) {
        // load this block's 16 Whh rows (16 x 256)
#pragma unroll
        for (int u = 0; u < 16; u += 4) {
            float4 v = *reinterpret_cast<const float4*>(Whh + (size_t)row * H_ + bq * 16 + u);
            w_s[rr][bq * 16 + u + 0] = v.x;
            w_s[rr][bq * 16 + u + 1] = v.y;
            w_s[rr][bq * 16 + u + 2] = v.z;
            w_s[rr][bq * 16 + u + 3] = v.w;
        }
        const float* __restrict__ hprev = hout + (size_t)(t - 1) * B_ * H_;
        const int bld = tid >> 2;            // batch for h loads
        const int kq4 = (tid & 3) * 4;
        for (int kc = 0; kc < H_; kc += 64) {
#pragma unroll
            for (int jj = 0; jj < 4; jj++) {
                int kk = kq4 + jj * 16;      // 0..60 step 4 coverage
                float4 v = *reinterpret_cast<const float4*>(hprev + (size_t)bld * H_ + kc + kk);
                h_s[kk + 0][bld] = v.x; h_s[kk + 1][bld] = v.y;
                h_s[kk + 2][bld] = v.z; h_s[kk + 3][bld] = v.w;
            }
            __syncthreads();
#pragma unroll 8
            for (int k = 0; k < 64; k++) {
                float w  = w_s[rr][kc + k];
                float4 hv = *reinterpret_cast<const float4*>(&h_s[k][b0]);
                acc0 += w * hv.x; acc1 += w * hv.y;
                acc2 += w * hv.z; acc3 += w * hv.w;
            }
            __syncthreads();
        }
    }

    // add x-part (bias already folded in)
    float xv[4];
#pragma unroll
    for (int q = 0; q < 4; q++) {
        int b = b0 + q;
        int m;
        if (dir == 0) {
            m = t * B_ + b;
        } else {
            int L = lens[b];
            int r = (t < L) ? (L - 1 - t) : t;
            m = r * B_ + b;
        }
        xv[q] = X[(size_t)m * G4_ + row];
    }
    gates_s[rr][b0 + 0] = acc0 + xv[0];
    gates_s[rr][b0 + 1] = acc1 + xv[1];
    gates_s[rr][b0 + 2] = acc2 + xv[2];
    gates_s[rr][b0 + 3] = acc3 + xv[3];
    __syncthreads();

    // pointwise: 256 threads = 64 batches x 4 channels
    {
        int b  = tid & 63;
        int ch = tid >> 6;
        float iv = gates_s[ch +  0][b];
        float fv = gates_s[ch +  4][b];
        float gv = gates_s[ch +  8][b];
        float ov = gates_s[ch + 12][b];
        float c_old = (t == 0) ? 0.0f : cst[b * H_ + j0 + ch];
        float cn = sigmoidf_(fv) * c_old + sigmoidf_(iv) * tanhf(gv);
        float hn = sigmoidf_(ov) * tanhf(cn);
        cst[b * H_ + j0 + ch] = cn;
        hout[(size_t)t * B_ * H_ + b * H_ + j0 + ch] = hn;
    }
}

// ---------------------------------------------------------------------------
// K4: u/w projections.  One block per (b,s); enc row assembled on the fly
//     (fwd[s,b] | bwd_rev[rev_idx,b]) * valid.  64 threads, 60 active dots.
// ---------------------------------------------------------------------------
__global__ void k_uw(const int* __restrict__ lens,
                     const float* __restrict__ Ua,
                     const float* __restrict__ Wa) {
    const int s = blockIdx.x;
    const int b = blockIdx.y;
    __shared__ float enc_s[2 * H_];

    const int L = lens[b];
    const bool valid = (s < L);
    const int ridx = valid ? (L - 1 - s) : s;
    const int tid = threadIdx.x;   // 64

    float4 f4 = make_float4(0.f, 0.f, 0.f, 0.f);
    float4 b4 = make_float4(0.f, 0.f, 0.f, 0.f);
    if (valid) {
        f4 = *reinterpret_cast<const float4*>(g_h + (size_t)s * B_ * H_ + b * H_ + tid * 4);
        b4 = *reinterpret_cast<const float4*>(g_h + (size_t)S_ * B_ * H_ +
                                              (size_t)ridx * B_ * H_ + b * H_ + tid * 4);
    }
    *reinterpret_cast<float4*>(&enc_s[tid * 4])       = f4;
    *reinterpret_cast<float4*>(&enc_s[H_ + tid * 4])  = b4;
    __syncthreads();

    if (tid < 2 * HID_) {
        const float* __restrict__ Wrow =
            (tid < HID_) ? (Ua + (size_t)tid * 2 * H_) : (Wa + (size_t)(tid - HID_) * 2 * H_);
        float acc = 0.f;
#pragma unroll 4
        for (int k = 0; k < 2 * H_; k += 4) {
            float4 wv = *reinterpret_cast<const float4*>(Wrow + k);
            float4 ev = *reinterpret_cast<const float4*>(&enc_s[k]);
            acc += wv.x * ev.x + wv.y * ev.y + wv.z * ev.z + wv.w * ev.w;
        }
        if (tid < HID_)
            g_U[((size_t)b * S_ + s) * HID_ + tid] = acc;
        else
            g_Wt[(size_t)b * HID_ * S_ + (size_t)(tid - HID_) * S_ + s] = acc;
    }
}

// ---------------------------------------------------------------------------
// K5: scores + predictions.  Block per (b,i), thread per j.
//     scores[b,i,j] = sum_k tanh(u[b,i,k] + w[b,j,k]) * va[k]
//     predictions   = (scores >= 0)  (== sigmoid(s) >= 0.5)
// ---------------------------------------------------------------------------
__global__ void k_scores(const float* __restrict__ va, float* __restrict__ out) {
    const int i = blockIdx.x;
    const int b = blockIdx.y;
    const int j = threadIdx.x;   // 128

    __shared__ float u_s[HID_];
    __shared__ float va_s[HID_];
    if (j < HID_) {
        u_s[j]  = g_U[((size_t)b * S_ + i) * HID_ + j];
        va_s[j] = va[j];
    }
    __syncthreads();

    const float* __restrict__ Wb = g_Wt + (size_t)b * HID_ * S_;
    float acc = 0.f;
#pragma unroll
    for (int k = 0; k < HID_; k++) {
        float wv = Wb[k * S_ + j];
        acc += tanhf(u_s[k] + wv) * va_s[k];
    }
    size_t idx = ((size_t)b * S_ + i) * S_ + j;
    out[idx] = acc;
    out[(size_t)B_ * S_ * S_ + idx] = (acc >= 0.0f) ? 1.0f : 0.0f;
}

// ---------------------------------------------------------------------------
extern "C" void kernel_launch(void* const* d_in, const int* in_sizes, int n_in,
                              void* d_out, int out_size) {
    const int*   concepts = (const int*)d_in[0];
    const int*   lens     = (const int*)d_in[1];
    const float* emb      = (const float*)d_in[2];
    const float* Wih_f    = (const float*)d_in[3];
    const float* Whh_f    = (const float*)d_in[4];
    const float* b_f      = (const float*)d_in[5];
    const float* Wih_b    = (const float*)d_in[6];
    const float* Whh_b    = (const float*)d_in[7];
    const float* b_b      = (const float*)d_in[8];
    const float* Ua       = (const float*)d_in[9];
    const float* Wa       = (const float*)d_in[10];
    const float* va       = (const float*)d_in[11];
    float* out = (float*)d_out;

    k_gather<<<S_ * B_, 64>>>(concepts, emb);
    k_xgemm<<<dim3(64, 8, 2), 256>>>(Wih_f, b_f, Wih_b, b_b);
    for (int t = 0; t < S_; ++t)
        k_step<<<dim3(64, 2), 256>>>(t, lens, Whh_f, Whh_b);
    k_uw<<<dim3(S_, B_), 64>>>(lens, Ua, Wa);
    k_scores<<<dim3(S_, B_), 128>>>(va, out);
}

// round 3
// speedup vs baseline: 1.2656x; 1.2656x over previous
#include <cuda_runtime.h>
#include <math.h>
#include <stdint.h>

typedef unsigned long long ull;

// Problem constants
constexpr int S_   = 128;   // sequence length
constexpr int B_   = 64;    // batch
constexpr int E_   = 256;   // embedding dim
constexpr int H_   = 256;   // hidden
constexpr int G4_  = 1024;  // 4*H (gates)
constexpr int HID_ = 30;    // attention hidden
constexpr int NCTA_DIR = 64;   // CTAs per direction in persistent step kernel

// Scratch (static device globals — no runtime allocation)
__device__ float g_emb[S_ * B_ * E_];        // (t,b,e)
__device__ float g_X[2 * S_ * B_ * G4_];     // x-projections per dir, bias folded in
__device__ float g_h[2 * S_ * B_ * H_];      // [dir][t][b][k]  (for K4)
__device__ float g_hT[2][2][H_][B_];         // ping-pong [dir][parity][k][b]
__device__ int   g_bar[2 * S_];              // grid-barrier arrival counters
__device__ float g_U[B_ * S_ * HID_];        // u = enc @ Ua^T
__device__ float g_Wt[B_ * HID_ * S_];       // w transposed: [b][k][s]

__device__ __forceinline__ float sigmoidf_(float x) { return 1.0f / (1.0f + expf(-x)); }

__device__ __forceinline__ void ffma2(ull& d, ull a, ull b) {
    asm volatile("fma.rn.f32x2 %0, %1, %2, %0;" : "+l"(d) : "l"(a), "l"(b));
}
__device__ __forceinline__ ull pack2(float lo, float hi) {
    ull r; asm("mov.b64 %0, {%1, %2};" : "=l"(r) : "f"(lo), "f"(hi)); return r;
}
__device__ __forceinline__ float2 unpack2(ull v) {
    float2 r; asm("mov.b64 {%0, %1}, %2;" : "=f"(r.x), "=f"(r.y) : "l"(v)); return r;
}
__device__ __forceinline__ void cp16(uint32_t smem_dst, const void* gsrc) {
    asm volatile("cp.async.cg.shared.global [%0], [%1], 16;" :: "r"(smem_dst), "l"(gsrc) : "memory");
}

// ---------------------------------------------------------------------------
// K0: zero the grid-barrier counters (stream-ordered before k_steps)
// ---------------------------------------------------------------------------
__global__ void k_zero_bar() {
    if (threadIdx.x < 2 * S_) g_bar[threadIdx.x] = 0;
}

// ---------------------------------------------------------------------------
// K1: embedding gather.  grid = S*B blocks, 64 threads (float4 row copy)
// ---------------------------------------------------------------------------
__global__ void k_gather(const int* __restrict__ concepts,
                         const float* __restrict__ table) {
    int tb  = blockIdx.x;                      // t*B + b
    int tok = concepts[tb];
    const float4* src = reinterpret_cast<const float4*>(table + (size_t)tok * E_);
    float4*       dst = reinterpret_cast<float4*>(g_emb + (size_t)tb * E_);
    dst[threadIdx.x] = src[threadIdx.x];
}

// ---------------------------------------------------------------------------
// K2: x-projection GEMM  X[dir] = emb @ Wih[dir]^T + b[dir]
//     M=8192, N=1024, K=256.  BM=BN=128, BK=16, 256 thr, 8x8 microtile,
//     packed f32x2 FMA in the inner product.
// ---------------------------------------------------------------------------
__global__ __launch_bounds__(256) void k_xgemm(const float* __restrict__ Wih_f,
                                               const float* __restrict__ b_f,
                                               const float* __restrict__ Wih_b,
                                               const float* __restrict__ b_b) {
    const int dir = blockIdx.z;
    const float* __restrict__ Wih  = dir ? Wih_b : Wih_f;
    const float* __restrict__ bias = dir ? b_b   : b_f;
    float* __restrict__ Xout = g_X + (size_t)dir * S_ * B_ * G4_;

    __shared__ float As[16][132];   // [k][m] k-major
    __shared__ float Bs[16][132];   // [k][n]

    const int m0  = blockIdx.x * 128;
    const int n0  = blockIdx.y * 128;
    const int tid = threadIdx.x;
    const int tx  = tid & 15;       // -> n
    const int ty  = tid >> 4;       // -> m

    ull acc2[8][4];
#pragma unroll
    for (int i = 0; i < 8; i++)
#pragma unroll
        for (int j = 0; j < 4; j++) acc2[i][j] = 0ull;

    for (int kc = 0; kc < E_; kc += 16) {
#pragma unroll
        for (int p = 0; p < 2; p++) {
            int q  = tid + p * 256;        // 0..511 quads
            int r  = q >> 2;               // row 0..127
            int kq = (q & 3) * 4;          // k quad
            float4 va = *reinterpret_cast<const float4*>(g_emb + (size_t)(m0 + r) * E_ + kc + kq);
            As[kq + 0][r] = va.x; As[kq + 1][r] = va.y;
            As[kq + 2][r] = va.z; As[kq + 3][r] = va.w;
            float4 vb = *reinterpret_cast<const float4*>(Wih + (size_t)(n0 + r) * E_ + kc + kq);
            Bs[kq + 0][r] = vb.x; Bs[kq + 1][r] = vb.y;
            Bs[kq + 2][r] = vb.z; Bs[kq + 3][r] = vb.w;
        }
        __syncthreads();
#pragma unroll
        for (int k = 0; k < 16; k++) {
            float4 a0 = *reinterpret_cast<const float4*>(&As[k][ty * 8]);
            float4 a1 = *reinterpret_cast<const float4*>(&As[k][ty * 8 + 4]);
            ulonglong2 bb0 = *reinterpret_cast<const ulonglong2*>(&Bs[k][tx * 8]);
            ulonglong2 bb1 = *reinterpret_cast<const ulonglong2*>(&Bs[k][tx * 8 + 4]);
            ull b2[4] = { bb0.x, bb0.y, bb1.x, bb1.y };
            float av[8] = { a0.x, a0.y, a0.z, a0.w, a1.x, a1.y, a1.z, a1.w };
#pragma unroll
            for (int i = 0; i < 8; i++) {
                ull ap = pack2(av[i], av[i]);
#pragma unroll
                for (int j = 0; j < 4; j++) ffma2(acc2[i][j], ap, b2[j]);
            }
        }
        __syncthreads();
    }

    // epilogue: add bias, contiguous float4 stores
    float bv[8];
#pragma unroll
    for (int j = 0; j < 8; j++) bv[j] = bias[n0 + tx * 8 + j];
#pragma unroll
    for (int i = 0; i < 8; i++) {
        int m = m0 + ty * 8 + i;
        float2 e0 = unpack2(acc2[i][0]);
        float2 e1 = unpack2(acc2[i][1]);
        float2 e2 = unpack2(acc2[i][2]);
        float2 e3 = unpack2(acc2[i][3]);
        float4 o0, o1;
        o0.x = e0.x + bv[0]; o0.y = e0.y + bv[1];
        o0.z = e1.x + bv[2]; o0.w = e1.y + bv[3];
        o1.x = e2.x + bv[4]; o1.y = e2.y + bv[5];
        o1.z = e3.x + bv[6]; o1.w = e3.y + bv[7];
        float* dst = Xout + (size_t)m * G4_ + n0 + tx * 8;
        *reinterpret_cast<float4*>(dst)     = o0;
        *reinterpret_cast<float4*>(dst + 4) = o1;
    }
}

// ---------------------------------------------------------------------------
// K3: persistent BiLSTM recurrence.  Grid = 128 CTAs (64 per dir), 256 thr.
//     CTA (dir, cb) owns channels [cb*4, cb*4+4) => 16 gate rows.
//     STATIC smem only (~45.8 KB).  Warp = 16 gate-rows x 2 batch-quads so
//     the h LDS.128 is a 2-address broadcast (1 wavefront).  Whh kept
//     unpacked in shared; {w,w} pair built with one mov (ALU pipe).
//     h passes between steps through ping-pong g_hT via cp.async (triple
//     buffer, 32-k chunks).  Per-dir bounded-spin grid barrier per step.
// ---------------------------------------------------------------------------
__global__ __launch_bounds__(256, 1) void k_steps(const int* __restrict__ lens,
                                                  const float* __restrict__ Whh_f,
                                                  const float* __restrict__ Whh_b) {
    __shared__ float w_s[16][260];      // 16640 B
    __shared__ float hbuf[3][32][64];   // 24576 B
    __shared__ float gates_s[16][68];   //  4352 B
    __shared__ int   lens_s[64];        //   256 B

    const int tid = threadIdx.x;
    const int dir = blockIdx.x >> 6;
    const int cb  = blockIdx.x & 63;
    const int j0  = cb * 4;
    const float* __restrict__ Whh = dir ? Whh_b : Whh_f;
    const float* __restrict__ X   = g_X + (size_t)dir * S_ * B_ * G4_;

    if (tid < B_) lens_s[tid] = lens[tid];

    // load this CTA's 16 Whh rows (unpacked)
    {
        int row  = tid >> 4;
        int gg   = row >> 2, ch = row & 3;
        int grw  = gg * H_ + j0 + ch;
        const float* src = Whh + (size_t)grw * H_;
        int k0 = (tid & 15) * 16;
#pragma unroll
        for (int u = 0; u < 16; u += 4) {
            float4 v = *reinterpret_cast<const float4*>(src + k0 + u);
            w_s[row][k0 + u + 0] = v.x;
            w_s[row][k0 + u + 1] = v.y;
            w_s[row][k0 + u + 2] = v.z;
            w_s[row][k0 + u + 3] = v.w;
        }
    }
    __syncthreads();

    const int r    = tid & 15;          // gate-row 0..15  (= gg*4 + ch)
    const int bq   = tid >> 4;          // batch quad 0..15
    const int b0   = bq * 4;
    const int gg   = r >> 2, ch = r & 3;
    const int grow = gg * H_ + j0 + ch; // global gate row
    const int pb   = tid & 63;          // pointwise batch
    const int pch  = tid >> 6;          // pointwise channel 0..3
    float creg = 0.0f;

    const int L0 = lens_s[b0], L1 = lens_s[b0 + 1], L2 = lens_s[b0 + 2], L3 = lens_s[b0 + 3];

    uint32_t hb_sa[3];
    hb_sa[0] = (uint32_t)__cvta_generic_to_shared(&hbuf[0][0][0]);
    hb_sa[1] = (uint32_t)__cvta_generic_to_shared(&hbuf[1][0][0]);
    hb_sa[2] = (uint32_t)__cvta_generic_to_shared(&hbuf[2][0][0]);

    float* __restrict__ houtB = g_h + (size_t)dir * S_ * B_ * H_;
    volatile int* barp = (volatile int*)(g_bar + dir * S_);
    const float* wr = &w_s[r][0];

    for (int t = 0; t < S_; ++t) {
        // X prefetch (latency hidden under chunk loop)
        float xv0, xv1, xv2, xv3;
        {
            int m0i, m1i, m2i, m3i;
            if (dir == 0) {
                int base = t * B_;
                m0i = base + b0; m1i = m0i + 1; m2i = m0i + 2; m3i = m0i + 3;
            } else {
                int r0 = (t < L0) ? (L0 - 1 - t) : t;
                int r1 = (t < L1) ? (L1 - 1 - t) : t;
                int r2 = (t < L2) ? (L2 - 1 - t) : t;
                int r3 = (t < L3) ? (L3 - 1 - t) : t;
                m0i = r0 * B_ + b0;     m1i = r1 * B_ + b0 + 1;
                m2i = r2 * B_ + b0 + 2; m3i = r3 * B_ + b0 + 3;
            }
            xv0 = X[(size_t)m0i * G4_ + grow];
            xv1 = X[(size_t)m1i * G4_ + grow];
            xv2 = X[(size_t)m2i * G4_ + grow];
            xv3 = X[(size_t)m3i * G4_ + grow];
        }

        ull acc0 = 0ull, acc1 = 0ull;
        if (t > 0) {
            const float* hsrc = &g_hT[dir][(t - 1) & 1][0][0];
            // prologue: chunks 0,1
#pragma unroll
            for (int p = 0; p < 2; ++p) {
                const float* s = hsrc + p * 2048 + tid * 4;
                cp16(hb_sa[p] + tid * 16, s);
                cp16(hb_sa[p] + (tid + 256) * 16, s + 1024);
                asm volatile("cp.async.commit_group;" ::: "memory");
            }
#pragma unroll 1
            for (int c = 0; c < 8; ++c) {
                if (c < 7) asm volatile("cp.async.wait_group 1;" ::: "memory");
                else       asm volatile("cp.async.wait_group 0;" ::: "memory");
                __syncthreads();
                if (c + 2 < 8) {
                    int p = (c + 2) % 3;
                    const float* s = hsrc + (c + 2) * 2048 + tid * 4;
                    cp16(hb_sa[p] + tid * 16, s);
                    cp16(hb_sa[p] + (tid + 256) * 16, s + 1024);
                    asm volatile("cp.async.commit_group;" ::: "memory");
                }
                const float* hb = &hbuf[c % 3][0][b0];
                const float* wc = wr + c * 32;
#pragma unroll
                for (int kk = 0; kk < 32; kk += 4) {
                    float4 wv = *reinterpret_cast<const float4*>(wc + kk);
                    {
                        ull wp = pack2(wv.x, wv.x);
                        ulonglong2 h2 = *reinterpret_cast<const ulonglong2*>(hb + (kk + 0) * 64);
                        ffma2(acc0, wp, h2.x); ffma2(acc1, wp, h2.y);
                    }
                    {
                        ull wp = pack2(wv.y, wv.y);
                        ulonglong2 h2 = *reinterpret_cast<const ulonglong2*>(hb + (kk + 1) * 64);
                        ffma2(acc0, wp, h2.x); ffma2(acc1, wp, h2.y);
                    }
                    {
                        ull wp = pack2(wv.z, wv.z);
                        ulonglong2 h2 = *reinterpret_cast<const ulonglong2*>(hb + (kk + 2) * 64);
                        ffma2(acc0, wp, h2.x); ffma2(acc1, wp, h2.y);
                    }
                    {
                        ull wp = pack2(wv.w, wv.w);
                        ulonglong2 h2 = *reinterpret_cast<const ulonglong2*>(hb + (kk + 3) * 64);
                        ffma2(acc0, wp, h2.x); ffma2(acc1, wp, h2.y);
                    }
                }
            }
        }

        float2 p0 = unpack2(acc0), p1 = unpack2(acc1);
        *reinterpret_cast<float4*>(&gates_s[r][b0]) =
            make_float4(p0.x + xv0, p0.y + xv1, p1.x + xv2, p1.y + xv3);
        __syncthreads();

        // pointwise: thread = (pch, pb)
        {
            float iv = gates_s[0 * 4 + pch][pb];
            float fv = gates_s[1 * 4 + pch][pb];
            float gv = gates_s[2 * 4 + pch][pb];
            float ov = gates_s[3 * 4 + pch][pb];
            float cn = sigmoidf_(fv) * creg + sigmoidf_(iv) * tanhf(gv);
            float hn = sigmoidf_(ov) * tanhf(cn);
            creg = cn;
            houtB[(size_t)t * B_ * H_ + pb * H_ + j0 + pch] = hn;
            g_hT[dir][t & 1][j0 + pch][pb] = hn;
        }

        // per-dir grid barrier (bounded spin; skip after last step)
        if (t < S_ - 1) {
            __syncthreads();
            if (tid == 0) {
                __threadfence();
                atomicAdd((int*)&barp[t], 1);
                int guard = 1 << 16;
                while (barp[t] < NCTA_DIR && --guard) { }
                __threadfence();
            }
            __syncthreads();
        }
    }
}

// ---------------------------------------------------------------------------
// K4: u/w projections.  One block per (b,s); enc row assembled on the fly.
// ---------------------------------------------------------------------------
__global__ void k_uw(const int* __restrict__ lens,
                     const float* __restrict__ Ua,
                     const float* __restrict__ Wa) {
    const int s = blockIdx.x;
    const int b = blockIdx.y;
    __shared__ float enc_s[2 * H_];

    const int L = lens[b];
    const bool valid = (s < L);
    const int ridx = valid ? (L - 1 - s) : s;
    const int tid = threadIdx.x;   // 64

    float4 f4 = make_float4(0.f, 0.f, 0.f, 0.f);
    float4 b4 = make_float4(0.f, 0.f, 0.f, 0.f);
    if (valid) {
        f4 = *reinterpret_cast<const float4*>(g_h + (size_t)s * B_ * H_ + b * H_ + tid * 4);
        b4 = *reinterpret_cast<const float4*>(g_h + (size_t)S_ * B_ * H_ +
                                              (size_t)ridx * B_ * H_ + b * H_ + tid * 4);
    }
    *reinterpret_cast<float4*>(&enc_s[tid * 4])       = f4;
    *reinterpret_cast<float4*>(&enc_s[H_ + tid * 4])  = b4;
    __syncthreads();

    if (tid < 2 * HID_) {
        const float* __restrict__ Wrow =
            (tid < HID_) ? (Ua + (size_t)tid * 2 * H_) : (Wa + (size_t)(tid - HID_) * 2 * H_);
        float acc = 0.f;
#pragma unroll 4
        for (int k = 0; k < 2 * H_; k += 4) {
            float4 wv = *reinterpret_cast<const float4*>(Wrow + k);
            float4 ev = *reinterpret_cast<const float4*>(&enc_s[k]);
            acc += wv.x * ev.x + wv.y * ev.y + wv.z * ev.z + wv.w * ev.w;
        }
        if (tid < HID_)
            g_U[((size_t)b * S_ + s) * HID_ + tid] = acc;
        else
            g_Wt[(size_t)b * HID_ * S_ + (size_t)(tid - HID_) * S_ + s] = acc;
    }
}

// ---------------------------------------------------------------------------
// K5: scores + predictions.
// ---------------------------------------------------------------------------
__global__ void k_scores(const float* __restrict__ va, float* __restrict__ out) {
    const int i = blockIdx.x;
    const int b = blockIdx.y;
    const int j = threadIdx.x;   // 128

    __shared__ float u_s[HID_];
    __shared__ float va_s[HID_];
    if (j < HID_) {
        u_s[j]  = g_U[((size_t)b * S_ + i) * HID_ + j];
        va_s[j] = va[j];
    }
    __syncthreads();

    const float* __restrict__ Wb = g_Wt + (size_t)b * HID_ * S_;
    float acc = 0.f;
#pragma unroll
    for (int k = 0; k < HID_; k++) {
        float wv = Wb[k * S_ + j];
        acc += tanhf(u_s[k] + wv) * va_s[k];
    }
    size_t idx = ((size_t)b * S_ + i) * S_ + j;
    out[idx] = acc;
    out[(size_t)B_ * S_ * S_ + idx] = (acc >= 0.0f) ? 1.0f : 0.0f;
}

// ---------------------------------------------------------------------------
extern "C" void kernel_launch(void* const* d_in, const int* in_sizes, int n_in,
                              void* d_out, int out_size) {
    const int*   concepts = (const int*)d_in[0];
    const int*   lens     = (const int*)d_in[1];
    const float* emb      = (const float*)d_in[2];
    const float* Wih_f    = (const float*)d_in[3];
    const float* Whh_f    = (const float*)d_in[4];
    const float* b_f      = (const float*)d_in[5];
    const float* Wih_b    = (const float*)d_in[6];
    const float* Whh_b    = (const float*)d_in[7];
    const float* b_b      = (const float*)d_in[8];
    const float* Ua       = (const float*)d_in[9];
    const float* Wa       = (const float*)d_in[10];
    const float* va       = (const float*)d_in[11];
    float* out = (float*)d_out;

    k_gather<<<S_ * B_, 64>>>(concepts, emb);
    k_xgemm<<<dim3(64, 8, 2), 256>>>(Wih_f, b_f, Wih_b, b_b);
    k_zero_bar<<<1, 256>>>();
    k_steps<<<2 * NCTA_DIR, 256>>>(lens, Whh_f, Whh_b);
    k_uw<<<dim3(S_, B_), 64>>>(lens, Ua, Wa);
    k_scores<<<dim3(S_, B_), 128>>>(va, out);
}

// round 4
// speedup vs baseline: 1.5459x; 1.2214x over previous
#include <cuda_runtime.h>
#include <math.h>
#include <stdint.h>

typedef unsigned long long ull;

// Problem constants
constexpr int S_   = 128;   // sequence length
constexpr int B_   = 64;    // batch
constexpr int E_   = 256;   // embedding dim
constexpr int H_   = 256;   // hidden
constexpr int G4_  = 1024;  // 4*H (gates)
constexpr int HID_ = 30;    // attention hidden
constexpr int NCTA_DIR = 64;   // CTAs per direction in persistent step kernel

// Scratch (static device globals — no runtime allocation)
__device__ float g_emb[S_ * B_ * E_];        // (t,b,e)
__device__ float g_X[2 * S_ * B_ * G4_];     // x-projections per dir, bias folded in
__device__ float g_h[2 * S_ * B_ * H_];      // [dir][t][b][k]  (for K4)
__device__ float g_hT[2][2][H_][B_];         // ping-pong [dir][parity][k][b]
__device__ int   g_bar[2 * S_];              // grid-barrier arrival counters
__device__ float g_U[B_ * S_ * HID_];        // u = enc @ Ua^T
__device__ float g_Wt[B_ * HID_ * S_];       // w transposed: [b][k][s]

__device__ __forceinline__ float sigmoidf_(float x) { return 1.0f / (1.0f + expf(-x)); }

// pure (non-volatile) packed fp32 math — scheduler may move these freely
__device__ __forceinline__ void ffma2(ull& d, ull a, ull b) {
    asm("fma.rn.f32x2 %0, %1, %2, %0;" : "+l"(d) : "l"(a), "l"(b));
}
__device__ __forceinline__ ull pack2(float lo, float hi) {
    ull r; asm("mov.b64 %0, {%1, %2};" : "=l"(r) : "f"(lo), "f"(hi)); return r;
}
__device__ __forceinline__ float2 unpack2(ull v) {
    float2 r; asm("mov.b64 {%0, %1}, %2;" : "=f"(r.x), "=f"(r.y) : "l"(v)); return r;
}
// L1-bypassing 16B load (h produced by other CTAs within this launch)
__device__ __forceinline__ void ldcg128(ull& x, ull& y, const float* p) {
    asm volatile("ld.global.cg.v2.u64 {%0, %1}, [%2];" : "=l"(x), "=l"(y) : "l"(p));
}
__device__ __forceinline__ void stcg32(float* p, float v) {
    asm volatile("st.global.cg.f32 [%0], %1;" :: "l"(p), "f"(v));
}

// ---------------------------------------------------------------------------
// K0: zero the grid-barrier counters (stream-ordered before k_steps)
// ---------------------------------------------------------------------------
__global__ void k_zero_bar() {
    if (threadIdx.x < 2 * S_) g_bar[threadIdx.x] = 0;
}

// ---------------------------------------------------------------------------
// K1: embedding gather.  grid = S*B blocks, 64 threads (float4 row copy)
// ---------------------------------------------------------------------------
__global__ void k_gather(const int* __restrict__ concepts,
                         const float* __restrict__ table) {
    int tb  = blockIdx.x;                      // t*B + b
    int tok = concepts[tb];
    const float4* src = reinterpret_cast<const float4*>(table + (size_t)tok * E_);
    float4*       dst = reinterpret_cast<float4*>(g_emb + (size_t)tb * E_);
    dst[threadIdx.x] = src[threadIdx.x];
}

// ---------------------------------------------------------------------------
// K2: x-projection GEMM  X[dir] = emb @ Wih[dir]^T + b[dir]
//     M=8192, N=1024, K=256.  BM=BN=128, BK=16, 256 thr, 8x8 microtile,
//     packed f32x2 FMA in the inner product.
// ---------------------------------------------------------------------------
__global__ __launch_bounds__(256) void k_xgemm(const float* __restrict__ Wih_f,
                                               const float* __restrict__ b_f,
                                               const float* __restrict__ Wih_b,
                                               const float* __restrict__ b_b) {
    const int dir = blockIdx.z;
    const float* __restrict__ Wih  = dir ? Wih_b : Wih_f;
    const float* __restrict__ bias = dir ? b_b   : b_f;
    float* __restrict__ Xout = g_X + (size_t)dir * S_ * B_ * G4_;

    __shared__ float As[16][132];   // [k][m] k-major
    __shared__ float Bs[16][132];   // [k][n]

    const int m0  = blockIdx.x * 128;
    const int n0  = blockIdx.y * 128;
    const int tid = threadIdx.x;
    const int tx  = tid & 15;       // -> n
    const int ty  = tid >> 4;       // -> m

    ull acc2[8][4];
#pragma unroll
    for (int i = 0; i < 8; i++)
#pragma unroll
        for (int j = 0; j < 4; j++) acc2[i][j] = 0ull;

    for (int kc = 0; kc < E_; kc += 16) {
#pragma unroll
        for (int p = 0; p < 2; p++) {
            int q  = tid + p * 256;        // 0..511 quads
            int r  = q >> 2;               // row 0..127
            int kq = (q & 3) * 4;          // k quad
            float4 va = *reinterpret_cast<const float4*>(g_emb + (size_t)(m0 + r) * E_ + kc + kq);
            As[kq + 0][r] = va.x; As[kq + 1][r] = va.y;
            As[kq + 2][r] = va.z; As[kq + 3][r] = va.w;
            float4 vb = *reinterpret_cast<const float4*>(Wih + (size_t)(n0 + r) * E_ + kc + kq);
            Bs[kq + 0][r] = vb.x; Bs[kq + 1][r] = vb.y;
            Bs[kq + 2][r] = vb.z; Bs[kq + 3][r] = vb.w;
        }
        __syncthreads();
#pragma unroll
        for (int k = 0; k < 16; k++) {
            float4 a0 = *reinterpret_cast<const float4*>(&As[k][ty * 8]);
            float4 a1 = *reinterpret_cast<const float4*>(&As[k][ty * 8 + 4]);
            ulonglong2 bb0 = *reinterpret_cast<const ulonglong2*>(&Bs[k][tx * 8]);
            ulonglong2 bb1 = *reinterpret_cast<const ulonglong2*>(&Bs[k][tx * 8 + 4]);
            ull b2[4] = { bb0.x, bb0.y, bb1.x, bb1.y };
            float av[8] = { a0.x, a0.y, a0.z, a0.w, a1.x, a1.y, a1.z, a1.w };
#pragma unroll
            for (int i = 0; i < 8; i++) {
                ull ap = pack2(av[i], av[i]);
#pragma unroll
                for (int j = 0; j < 4; j++) ffma2(acc2[i][j], ap, b2[j]);
            }
        }
        __syncthreads();
    }

    // epilogue: add bias, contiguous float4 stores
    float bv[8];
#pragma unroll
    for (int j = 0; j < 8; j++) bv[j] = bias[n0 + tx * 8 + j];
#pragma unroll
    for (int i = 0; i < 8; i++) {
        int m = m0 + ty * 8 + i;
        float2 e0 = unpack2(acc2[i][0]);
        float2 e1 = unpack2(acc2[i][1]);
        float2 e2 = unpack2(acc2[i][2]);
        float2 e3 = unpack2(acc2[i][3]);
        float4 o0, o1;
        o0.x = e0.x + bv[0]; o0.y = e0.y + bv[1];
        o0.z = e1.x + bv[2]; o0.w = e1.y + bv[3];
        o1.x = e2.x + bv[4]; o1.y = e2.y + bv[5];
        o1.z = e3.x + bv[6]; o1.w = e3.y + bv[7];
        float* dst = Xout + (size_t)m * G4_ + n0 + tx * 8;
        *reinterpret_cast<float4*>(dst)     = o0;
        *reinterpret_cast<float4*>(dst + 4) = o1;
    }
}

// ---------------------------------------------------------------------------
// K3: persistent BiLSTM recurrence.  Grid = 128 CTAs (64 per dir), 256 thr.
//     CTA (dir, cb) owns channels [cb*4, cb*4+4) => 16 gate rows.
//     Thread decomposition of the 16x64x256 step GEMM:
//       (ks 0..3 k-slices) x (rq 0..3 row-quads) x (bq 0..15 batch-quads)
//     Per thread: 4 rows x 4 batches over 64 k; per k:
//       1x ld.global.cg 16B of h[k][b0..b0+3]  (straight from L2, no staging)
//       1x LDS.128 of w_s[k][r0..r0+3]          (transposed Whh, broadcast)
//       8x fma.rn.f32x2 into 8 independent accumulator chains.
//     k-split partials reduced through smem once per step; pointwise fused.
//     Per-dir grid barrier = red.release.gpu + ld.acquire.gpu poll (bounded).
// ---------------------------------------------------------------------------
__global__ __launch_bounds__(256, 1) void k_steps(const int* __restrict__ lens,
                                                  const float* __restrict__ Whh_f,
                                                  const float* __restrict__ Whh_b) {
    __shared__ float w_s[256][16];        // [k][row]  16 KB (transposed Whh slice)
    __shared__ float part_s[4][16][64];   // k-slice partial gates  16 KB
    __shared__ int   lens_s[64];

    const int tid = threadIdx.x;
    const int dir = blockIdx.x >> 6;
    const int cb  = blockIdx.x & 63;
    const int j0  = cb * 4;
    const float* __restrict__ Whh = dir ? Whh_b : Whh_f;
    const float* __restrict__ X   = g_X + (size_t)dir * S_ * B_ * G4_;

    if (tid < B_) lens_s[tid] = lens[tid];

    // load this CTA's 16 Whh rows TRANSPOSED into w_s[k][row]
    {
        int row = tid >> 4;                 // 0..15 (= gate*4 + ch)
        int gg  = row >> 2, ch = row & 3;
        int grw = gg * H_ + j0 + ch;
        const float* src = Whh + (size_t)grw * H_ + (tid & 15) * 16;
#pragma unroll
        for (int u = 0; u < 16; u += 4) {
            float4 v = *reinterpret_cast<const float4*>(src + u);
            int k0 = (tid & 15) * 16 + u;
            w_s[k0 + 0][row] = v.x;
            w_s[k0 + 1][row] = v.y;
            w_s[k0 + 2][row] = v.z;
            w_s[k0 + 3][row] = v.w;
        }
    }
    __syncthreads();

    // GEMM-side ids
    const int ks = tid >> 6;           // k-slice 0..3
    const int rq = (tid >> 4) & 3;     // row quad 0..3
    const int bq = tid & 15;           // batch quad 0..15
    const int r0 = rq * 4;
    const int b0 = bq * 4;
    const int kbase = ks * 64;

    // pointwise-side ids (thread = (pch, pb))
    const int pch = tid >> 6;          // 0..3 channel within CTA
    const int pb  = tid & 63;          // batch
    const int Lp  = lens_s[pb];
    float creg = 0.0f;

    float* __restrict__ houtB = g_h + (size_t)dir * S_ * B_ * H_;
    int* barp = g_bar + dir * S_;

    for (int t = 0; t < S_; ++t) {
        // X prefetch for the pointwise thread (independent of h / barrier)
        float xg0, xg1, xg2, xg3;
        {
            int m;
            if (dir == 0) m = t * B_ + pb;
            else { int rr = (t < Lp) ? (Lp - 1 - t) : t; m = rr * B_ + pb; }
            const float* Xm = X + (size_t)m * G4_ + j0 + pch;
            xg0 = Xm[0 * H_]; xg1 = Xm[1 * H_]; xg2 = Xm[2 * H_]; xg3 = Xm[3 * H_];
        }

        if (t > 0) {
            ull a00 = 0, a01 = 0, a10 = 0, a11 = 0, a20 = 0, a21 = 0, a30 = 0, a31 = 0;
            const float* hsrc = &g_hT[dir][(t - 1) & 1][0][0] + (size_t)kbase * 64 + b0;
#pragma unroll 16
            for (int kk = 0; kk < 64; ++kk) {
                ull hx, hy;
                ldcg128(hx, hy, hsrc + kk * 64);
                float4 wv = *reinterpret_cast<const float4*>(&w_s[kbase + kk][r0]);
                ull w0 = pack2(wv.x, wv.x), w1 = pack2(wv.y, wv.y);
                ull w2 = pack2(wv.z, wv.z), w3 = pack2(wv.w, wv.w);
                ffma2(a00, w0, hx); ffma2(a01, w0, hy);
                ffma2(a10, w1, hx); ffma2(a11, w1, hy);
                ffma2(a20, w2, hx); ffma2(a21, w2, hy);
                ffma2(a30, w3, hx); ffma2(a31, w3, hy);
            }
            // write 4x4 partial tile
            float2 l0 = unpack2(a00), h0 = unpack2(a01);
            float2 l1 = unpack2(a10), h1 = unpack2(a11);
            float2 l2 = unpack2(a20), h2 = unpack2(a21);
            float2 l3 = unpack2(a30), h3 = unpack2(a31);
            *reinterpret_cast<float4*>(&part_s[ks][r0 + 0][b0]) = make_float4(l0.x, l0.y, h0.x, h0.y);
            *reinterpret_cast<float4*>(&part_s[ks][r0 + 1][b0]) = make_float4(l1.x, l1.y, h1.x, h1.y);
            *reinterpret_cast<float4*>(&part_s[ks][r0 + 2][b0]) = make_float4(l2.x, l2.y, h2.x, h2.y);
            *reinterpret_cast<float4*>(&part_s[ks][r0 + 3][b0]) = make_float4(l3.x, l3.y, h3.x, h3.y);
            __syncthreads();
        }

        // gates + pointwise for (pch, pb)
        {
            float gv0 = xg0, gv1 = xg1, gv2 = xg2, gv3 = xg3;
            if (t > 0) {
#pragma unroll
                for (int s = 0; s < 4; ++s) {
                    gv0 += part_s[s][0 * 4 + pch][pb];
                    gv1 += part_s[s][1 * 4 + pch][pb];
                    gv2 += part_s[s][2 * 4 + pch][pb];
                    gv3 += part_s[s][3 * 4 + pch][pb];
                }
            }
            float cn = sigmoidf_(gv1) * creg + sigmoidf_(gv0) * tanhf(gv2);
            float hn = sigmoidf_(gv3) * tanhf(cn);
            creg = cn;
            houtB[(size_t)t * B_ * H_ + pb * H_ + j0 + pch] = hn;
            stcg32(&g_hT[dir][t & 1][j0 + pch][pb], hn);
        }

        // per-dir grid barrier (release/acquire, bounded spin)
        if (t < S_ - 1) {
            __syncthreads();
            if (tid == 0) {
                asm volatile("red.release.gpu.global.add.s32 [%0], 1;" :: "l"(barp + t) : "memory");
                int guard = 1 << 20;
                int v;
                do {
                    asm volatile("ld.acquire.gpu.global.s32 %0, [%1];" : "=r"(v) : "l"(barp + t) : "memory");
                } while (v < NCTA_DIR && --guard);
            }
            __syncthreads();
        }
    }
}

// ---------------------------------------------------------------------------
// K4: u/w projections.  One block per (b,s); enc row assembled on the fly.
// ---------------------------------------------------------------------------
__global__ void k_uw(const int* __restrict__ lens,
                     const float* __restrict__ Ua,
                     const float* __restrict__ Wa) {
    const int s = blockIdx.x;
    const int b = blockIdx.y;
    __shared__ float enc_s[2 * H_];

    const int L = lens[b];
    const bool valid = (s < L);
    const int ridx = valid ? (L - 1 - s) : s;
    const int tid = threadIdx.x;   // 64

    float4 f4 = make_float4(0.f, 0.f, 0.f, 0.f);
    float4 b4 = make_float4(0.f, 0.f, 0.f, 0.f);
    if (valid) {
        f4 = *reinterpret_cast<const float4*>(g_h + (size_t)s * B_ * H_ + b * H_ + tid * 4);
        b4 = *reinterpret_cast<const float4*>(g_h + (size_t)S_ * B_ * H_ +
                                              (size_t)ridx * B_ * H_ + b * H_ + tid * 4);
    }
    *reinterpret_cast<float4*>(&enc_s[tid * 4])       = f4;
    *reinterpret_cast<float4*>(&enc_s[H_ + tid * 4])  = b4;
    __syncthreads();

    if (tid < 2 * HID_) {
        const float* __restrict__ Wrow =
            (tid < HID_) ? (Ua + (size_t)tid * 2 * H_) : (Wa + (size_t)(tid - HID_) * 2 * H_);
        float acc = 0.f;
#pragma unroll 4
        for (int k = 0; k < 2 * H_; k += 4) {
            float4 wv = *reinterpret_cast<const float4*>(Wrow + k);
            float4 ev = *reinterpret_cast<const float4*>(&enc_s[k]);
            acc += wv.x * ev.x + wv.y * ev.y + wv.z * ev.z + wv.w * ev.w;
        }
        if (tid < HID_)
            g_U[((size_t)b * S_ + s) * HID_ + tid] = acc;
        else
            g_Wt[(size_t)b * HID_ * S_ + (size_t)(tid - HID_) * S_ + s] = acc;
    }
}

// ---------------------------------------------------------------------------
// K5: scores + predictions.
// ---------------------------------------------------------------------------
__global__ void k_scores(const float* __restrict__ va, float* __restrict__ out) {
    const int i = blockIdx.x;
    const int b = blockIdx.y;
    const int j = threadIdx.x;   // 128

    __shared__ float u_s[HID_];
    __shared__ float va_s[HID_];
    if (j < HID_) {
        u_s[j]  = g_U[((size_t)b * S_ + i) * HID_ + j];
        va_s[j] = va[j];
    }
    __syncthreads();

    const float* __restrict__ Wb = g_Wt + (size_t)b * HID_ * S_;
    float acc = 0.f;
#pragma unroll
    for (int k = 0; k < HID_; k++) {
        float wv = Wb[k * S_ + j];
        acc += tanhf(u_s[k] + wv) * va_s[k];
    }
    size_t idx = ((size_t)b * S_ + i) * S_ + j;
    out[idx] = acc;
    out[(size_t)B_ * S_ * S_ + idx] = (acc >= 0.0f) ? 1.0f : 0.0f;
}

// ---------------------------------------------------------------------------
extern "C" void kernel_launch(void* const* d_in, const int* in_sizes, int n_in,
                              void* d_out, int out_size) {
    const int*   concepts = (const int*)d_in[0];
    const int*   lens     = (const int*)d_in[1];
    const float* emb      = (const float*)d_in[2];
    const float* Wih_f    = (const float*)d_in[3];
    const float* Whh_f    = (const float*)d_in[4];
    const float* b_f      = (const float*)d_in[5];
    const float* Wih_b    = (const float*)d_in[6];
    const float* Whh_b    = (const float*)d_in[7];
    const float* b_b      = (const float*)d_in[8];
    const float* Ua       = (const float*)d_in[9];
    const float* Wa       = (const float*)d_in[10];
    const float* va       = (const float*)d_in[11];
    float* out = (float*)d_out;

    k_gather<<<S_ * B_, 64>>>(concepts, emb);
    k_xgemm<<<dim3(64, 8, 2), 256>>>(Wih_f, b_f, Wih_b, b_b);
    k_zero_bar<<<1, 256>>>();
    k_steps<<<2 * NCTA_DIR, 256>>>(lens, Whh_f, Whh_b);
    k_uw<<<dim3(S_, B_), 64>>>(lens, Ua, Wa);
    k_scores<<<dim3(S_, B_), 128>>>(va, out);
}

// round 5
// speedup vs baseline: 1.5891x; 1.0279x over previous
#include <cuda_runtime.h>
#include <math.h>
#include <stdint.h>

typedef unsigned long long ull;

// Problem constants
constexpr int S_   = 128;   // sequence length
constexpr int B_   = 64;    // batch
constexpr int E_   = 256;   // embedding dim
constexpr int H_   = 256;   // hidden
constexpr int G4_  = 1024;  // 4*H (gates)
constexpr int HID_ = 30;    // attention hidden
constexpr int NCTA_DIR = 64;   // CTAs per direction in persistent step kernel

// Scratch (static device globals — no runtime allocation)
__device__ float g_emb[S_ * B_ * E_];        // (t,b,e)
__device__ float g_X[2 * S_ * B_ * G4_];     // x-projections per dir, bias folded in
__device__ float g_h[2 * S_ * B_ * H_];      // [dir][t][b][k]  (for K4)
__device__ float g_hT[2][2][H_][B_];         // ping-pong [dir][parity][k][b]
__device__ int   g_bar[2 * S_];              // grid-barrier arrival counters
__device__ float g_U[B_ * S_ * HID_];        // u = enc @ Ua^T
__device__ float g_Wt[B_ * HID_ * S_];       // w transposed: [b][k][s]

__device__ __forceinline__ float sigmoidf_(float x) { return 1.0f / (1.0f + expf(-x)); }

// pure (non-volatile) packed fp32 math — scheduler may move these freely
__device__ __forceinline__ void ffma2(ull& d, ull a, ull b) {
    asm("fma.rn.f32x2 %0, %1, %2, %0;" : "+l"(d) : "l"(a), "l"(b));
}
__device__ __forceinline__ ull pack2(float lo, float hi) {
    ull r; asm("mov.b64 %0, {%1, %2};" : "=l"(r) : "f"(lo), "f"(hi)); return r;
}
__device__ __forceinline__ float2 unpack2(ull v) {
    float2 r; asm("mov.b64 {%0, %1}, %2;" : "=f"(r.x), "=f"(r.y) : "l"(v)); return r;
}
// L1-bypassing 16B load (h produced by other CTAs within this launch)
__device__ __forceinline__ void ldcg128(ull& x, ull& y, const float* p) {
    asm volatile("ld.global.cg.v2.u64 {%0, %1}, [%2];" : "=l"(x), "=l"(y) : "l"(p));
}
__device__ __forceinline__ void stcg32(float* p, float v) {
    asm volatile("st.global.cg.f32 [%0], %1;" :: "l"(p), "f"(v));
}

// ---------------------------------------------------------------------------
// K0: zero the grid-barrier counters (stream-ordered before k_steps)
// ---------------------------------------------------------------------------
__global__ void k_zero_bar() {
    if (threadIdx.x < 2 * S_) g_bar[threadIdx.x] = 0;
}

// ---------------------------------------------------------------------------
// K1: embedding gather.  grid = S*B blocks, 64 threads (float4 row copy)
// ---------------------------------------------------------------------------
__global__ void k_gather(const int* __restrict__ concepts,
                         const float* __restrict__ table) {
    int tb  = blockIdx.x;                      // t*B + b
    int tok = concepts[tb];
    const float4* src = reinterpret_cast<const float4*>(table + (size_t)tok * E_);
    float4*       dst = reinterpret_cast<float4*>(g_emb + (size_t)tb * E_);
    dst[threadIdx.x] = src[threadIdx.x];
}

// ---------------------------------------------------------------------------
// K2: x-projection GEMM  X[dir] = emb @ Wih[dir]^T + b[dir]
//     M=8192, N=1024, K=256.  BM=BN=128, BK=16, 256 thr, 8x8 microtile,
//     packed f32x2 FMA in the inner product.
// ---------------------------------------------------------------------------
__global__ __launch_bounds__(256) void k_xgemm(const float* __restrict__ Wih_f,
                                               const float* __restrict__ b_f,
                                               const float* __restrict__ Wih_b,
                                               const float* __restrict__ b_b) {
    const int dir = blockIdx.z;
    const float* __restrict__ Wih  = dir ? Wih_b : Wih_f;
    const float* __restrict__ bias = dir ? b_b   : b_f;
    float* __restrict__ Xout = g_X + (size_t)dir * S_ * B_ * G4_;

    __shared__ float As[16][132];   // [k][m] k-major
    __shared__ float Bs[16][132];   // [k][n]

    const int m0  = blockIdx.x * 128;
    const int n0  = blockIdx.y * 128;
    const int tid = threadIdx.x;
    const int tx  = tid & 15;       // -> n
    const int ty  = tid >> 4;       // -> m

    ull acc2[8][4];
#pragma unroll
    for (int i = 0; i < 8; i++)
#pragma unroll
        for (int j = 0; j < 4; j++) acc2[i][j] = 0ull;

    for (int kc = 0; kc < E_; kc += 16) {
#pragma unroll
        for (int p = 0; p < 2; p++) {
            int q  = tid + p * 256;        // 0..511 quads
            int r  = q >> 2;               // row 0..127
            int kq = (q & 3) * 4;          // k quad
            float4 va = *reinterpret_cast<const float4*>(g_emb + (size_t)(m0 + r) * E_ + kc + kq);
            As[kq + 0][r] = va.x; As[kq + 1][r] = va.y;
            As[kq + 2][r] = va.z; As[kq + 3][r] = va.w;
            float4 vb = *reinterpret_cast<const float4*>(Wih + (size_t)(n0 + r) * E_ + kc + kq);
            Bs[kq + 0][r] = vb.x; Bs[kq + 1][r] = vb.y;
            Bs[kq + 2][r] = vb.z; Bs[kq + 3][r] = vb.w;
        }
        __syncthreads();
#pragma unroll
        for (int k = 0; k < 16; k++) {
            float4 a0 = *reinterpret_cast<const float4*>(&As[k][ty * 8]);
            float4 a1 = *reinterpret_cast<const float4*>(&As[k][ty * 8 + 4]);
            ulonglong2 bb0 = *reinterpret_cast<const ulonglong2*>(&Bs[k][tx * 8]);
            ulonglong2 bb1 = *reinterpret_cast<const ulonglong2*>(&Bs[k][tx * 8 + 4]);
            ull b2[4] = { bb0.x, bb0.y, bb1.x, bb1.y };
            float av[8] = { a0.x, a0.y, a0.z, a0.w, a1.x, a1.y, a1.z, a1.w };
#pragma unroll
            for (int i = 0; i < 8; i++) {
                ull ap = pack2(av[i], av[i]);
#pragma unroll
                for (int j = 0; j < 4; j++) ffma2(acc2[i][j], ap, b2[j]);
            }
        }
        __syncthreads();
    }

    // epilogue: add bias, contiguous float4 stores
    float bv[8];
#pragma unroll
    for (int j = 0; j < 8; j++) bv[j] = bias[n0 + tx * 8 + j];
#pragma unroll
    for (int i = 0; i < 8; i++) {
        int m = m0 + ty * 8 + i;
        float2 e0 = unpack2(acc2[i][0]);
        float2 e1 = unpack2(acc2[i][1]);
        float2 e2 = unpack2(acc2[i][2]);
        float2 e3 = unpack2(acc2[i][3]);
        float4 o0, o1;
        o0.x = e0.x + bv[0]; o0.y = e0.y + bv[1];
        o0.z = e1.x + bv[2]; o0.w = e1.y + bv[3];
        o1.x = e2.x + bv[4]; o1.y = e2.y + bv[5];
        o1.z = e3.x + bv[6]; o1.w = e3.y + bv[7];
        float* dst = Xout + (size_t)m * G4_ + n0 + tx * 8;
        *reinterpret_cast<float4*>(dst)     = o0;
        *reinterpret_cast<float4*>(dst + 4) = o1;
    }
}

// ---------------------------------------------------------------------------
// K3: persistent BiLSTM recurrence.  Grid = 128 CTAs (64 per dir), 512 thr.
//     CTA (dir, cb) owns channels [cb*4, cb*4+4) => 16 gate rows.
//     Thread decomposition of the 16x64x256 step GEMM:
//       (ks 0..7 k-slices) x (rq 0..3 row-quads) x (bq 0..15 batch-quads)
//     Per thread: 4 rows x 4 batches over 32 k; per k:
//       1x ld.global.cg 16B of h[k][b0..b0+3]  (straight from L2, no staging)
//       1x LDS.128 of w_s[k][r0..r0+3]          (transposed Whh, broadcast)
//       8x fma.rn.f32x2 into 8 independent accumulator chains.
//     4 warps/SMSP (vs 2 in R4) to hide the ~240-cycle L2 load latency.
//     k-split partials reduced through smem once per step; pointwise fused.
//     Per-dir grid barrier = red.release.gpu + ld.acquire.gpu poll (bounded).
// ---------------------------------------------------------------------------
__global__ __launch_bounds__(512, 1) void k_steps(const int* __restrict__ lens,
                                                  const float* __restrict__ Whh_f,
                                                  const float* __restrict__ Whh_b) {
    __shared__ float w_s[256][16];        // [k][row]  16 KB (transposed Whh slice)
    __shared__ float part_s[8][16][64];   // k-slice partial gates  32 KB

    const int tid = threadIdx.x;
    const int dir = blockIdx.x >> 6;
    const int cb  = blockIdx.x & 63;
    const int j0  = cb * 4;
    const float* __restrict__ Whh = dir ? Whh_b : Whh_f;
    const float* __restrict__ X   = g_X + (size_t)dir * S_ * B_ * G4_;

    // load this CTA's 16 Whh rows TRANSPOSED into w_s[k][row]
    {
        int row = tid >> 5;                 // 0..15 (= gate*4 + ch)
        int gg  = row >> 2, ch = row & 3;
        int grw = gg * H_ + j0 + ch;
        const float* src = Whh + (size_t)grw * H_ + (tid & 31) * 8;
#pragma unroll
        for (int u = 0; u < 8; u += 4) {
            float4 v = *reinterpret_cast<const float4*>(src + u);
            int k0 = (tid & 31) * 8 + u;
            w_s[k0 + 0][row] = v.x;
            w_s[k0 + 1][row] = v.y;
            w_s[k0 + 2][row] = v.z;
            w_s[k0 + 3][row] = v.w;
        }
    }
    __syncthreads();

    // GEMM-side ids: 512 = ks(8) x rq(4) x bq(16)
    const int ks = tid >> 6;           // k-slice 0..7 (32 k each)
    const int rq = (tid >> 4) & 3;     // row quad 0..3
    const int bq = tid & 15;           // batch quad 0..15
    const int r0 = rq * 4;
    const int b0 = bq * 4;
    const int kbase = ks * 32;

    // pointwise-side ids (threads < 256: thread = (pch, pb))
    const bool pw  = (tid < 256);
    const int  pch = tid >> 6;         // 0..3 channel within CTA (valid when pw)
    const int  pb  = tid & 63;         // batch
    const int  Lp  = pw ? __ldg(lens + pb) : 0;
    float creg = 0.0f;

    float* __restrict__ houtB = g_h + (size_t)dir * S_ * B_ * H_;
    int* barp = g_bar + dir * S_;

    for (int t = 0; t < S_; ++t) {
        // X prefetch for the pointwise thread (independent of h / barrier)
        float xg0 = 0.f, xg1 = 0.f, xg2 = 0.f, xg3 = 0.f;
        if (pw) {
            int m;
            if (dir == 0) m = t * B_ + pb;
            else { int rr = (t < Lp) ? (Lp - 1 - t) : t; m = rr * B_ + pb; }
            const float* Xm = X + (size_t)m * G4_ + j0 + pch;
            xg0 = Xm[0 * H_]; xg1 = Xm[1 * H_]; xg2 = Xm[2 * H_]; xg3 = Xm[3 * H_];
        }

        if (t > 0) {
            ull a00 = 0, a01 = 0, a10 = 0, a11 = 0, a20 = 0, a21 = 0, a30 = 0, a31 = 0;
            const float* hsrc = &g_hT[dir][(t - 1) & 1][0][0] + (size_t)kbase * 64 + b0;
#pragma unroll 8
            for (int kk = 0; kk < 32; ++kk) {
                ull hx, hy;
                ldcg128(hx, hy, hsrc + kk * 64);
                float4 wv = *reinterpret_cast<const float4*>(&w_s[kbase + kk][r0]);
                ull w0 = pack2(wv.x, wv.x), w1 = pack2(wv.y, wv.y);
                ull w2 = pack2(wv.z, wv.z), w3 = pack2(wv.w, wv.w);
                ffma2(a00, w0, hx); ffma2(a01, w0, hy);
                ffma2(a10, w1, hx); ffma2(a11, w1, hy);
                ffma2(a20, w2, hx); ffma2(a21, w2, hy);
                ffma2(a30, w3, hx); ffma2(a31, w3, hy);
            }
            // write 4x4 partial tile
            float2 l0 = unpack2(a00), h0 = unpack2(a01);
            float2 l1 = unpack2(a10), h1 = unpack2(a11);
            float2 l2 = unpack2(a20), h2 = unpack2(a21);
            float2 l3 = unpack2(a30), h3 = unpack2(a31);
            *reinterpret_cast<float4*>(&part_s[ks][r0 + 0][b0]) = make_float4(l0.x, l0.y, h0.x, h0.y);
            *reinterpret_cast<float4*>(&part_s[ks][r0 + 1][b0]) = make_float4(l1.x, l1.y, h1.x, h1.y);
            *reinterpret_cast<float4*>(&part_s[ks][r0 + 2][b0]) = make_float4(l2.x, l2.y, h2.x, h2.y);
            *reinterpret_cast<float4*>(&part_s[ks][r0 + 3][b0]) = make_float4(l3.x, l3.y, h3.x, h3.y);
            __syncthreads();
        }

        // gates + pointwise for (pch, pb)
        if (pw) {
            float gv0 = xg0, gv1 = xg1, gv2 = xg2, gv3 = xg3;
            if (t > 0) {
#pragma unroll
                for (int s = 0; s < 8; ++s) {
                    gv0 += part_s[s][0 * 4 + pch][pb];
                    gv1 += part_s[s][1 * 4 + pch][pb];
                    gv2 += part_s[s][2 * 4 + pch][pb];
                    gv3 += part_s[s][3 * 4 + pch][pb];
                }
            }
            float cn = sigmoidf_(gv1) * creg + sigmoidf_(gv0) * tanhf(gv2);
            float hn = sigmoidf_(gv3) * tanhf(cn);
            creg = cn;
            houtB[(size_t)t * B_ * H_ + pb * H_ + j0 + pch] = hn;
            stcg32(&g_hT[dir][t & 1][j0 + pch][pb], hn);
        }

        // per-dir grid barrier (release/acquire, bounded spin)
        if (t < S_ - 1) {
            __syncthreads();
            if (tid == 0) {
                asm volatile("red.release.gpu.global.add.s32 [%0], 1;" :: "l"(barp + t) : "memory");
                int guard = 1 << 20;
                int v;
                do {
                    asm volatile("ld.acquire.gpu.global.s32 %0, [%1];" : "=r"(v) : "l"(barp + t) : "memory");
                } while (v < NCTA_DIR && --guard);
            }
            __syncthreads();
        }
    }
}

// ---------------------------------------------------------------------------
// K4: u/w projections.  One block per (b,s); enc row assembled on the fly.
// ---------------------------------------------------------------------------
__global__ void k_uw(const int* __restrict__ lens,
                     const float* __restrict__ Ua,
                     const float* __restrict__ Wa) {
    const int s = blockIdx.x;
    const int b = blockIdx.y;
    __shared__ float enc_s[2 * H_];

    const int L = lens[b];
    const bool valid = (s < L);
    const int ridx = valid ? (L - 1 - s) : s;
    const int tid = threadIdx.x;   // 64

    float4 f4 = make_float4(0.f, 0.f, 0.f, 0.f);
    float4 b4 = make_float4(0.f, 0.f, 0.f, 0.f);
    if (valid) {
        f4 = *reinterpret_cast<const float4*>(g_h + (size_t)s * B_ * H_ + b * H_ + tid * 4);
        b4 = *reinterpret_cast<const float4*>(g_h + (size_t)S_ * B_ * H_ +
                                              (size_t)ridx * B_ * H_ + b * H_ + tid * 4);
    }
    *reinterpret_cast<float4*>(&enc_s[tid * 4])       = f4;
    *reinterpret_cast<float4*>(&enc_s[H_ + tid * 4])  = b4;
    __syncthreads();

    if (tid < 2 * HID_) {
        const float* __restrict__ Wrow =
            (tid < HID_) ? (Ua + (size_t)tid * 2 * H_) : (Wa + (size_t)(tid - HID_) * 2 * H_);
        float acc = 0.f;
#pragma unroll 4
        for (int k = 0; k < 2 * H_; k += 4) {
            float4 wv = *reinterpret_cast<const float4*>(Wrow + k);
            float4 ev = *reinterpret_cast<const float4*>(&enc_s[k]);
            acc += wv.x * ev.x + wv.y * ev.y + wv.z * ev.z + wv.w * ev.w;
        }
        if (tid < HID_)
            g_U[((size_t)b * S_ + s) * HID_ + tid] = acc;
        else
            g_Wt[(size_t)b * HID_ * S_ + (size_t)(tid - HID_) * S_ + s] = acc;
    }
}

// ---------------------------------------------------------------------------
// K5: scores + predictions.
// ---------------------------------------------------------------------------
__global__ void k_scores(const float* __restrict__ va, float* __restrict__ out) {
    const int i = blockIdx.x;
    const int b = blockIdx.y;
    const int j = threadIdx.x;   // 128

    __shared__ float u_s[HID_];
    __shared__ float va_s[HID_];
    if (j < HID_) {
        u_s[j]  = g_U[((size_t)b * S_ + i) * HID_ + j];
        va_s[j] = va[j];
    }
    __syncthreads();

    const float* __restrict__ Wb = g_Wt + (size_t)b * HID_ * S_;
    float acc = 0.f;
#pragma unroll
    for (int k = 0; k < HID_; k++) {
        float wv = Wb[k * S_ + j];
        acc += tanhf(u_s[k] + wv) * va_s[k];
    }
    size_t idx = ((size_t)b * S_ + i) * S_ + j;
    out[idx] = acc;
    out[(size_t)B_ * S_ * S_ + idx] = (acc >= 0.0f) ? 1.0f : 0.0f;
}

// ---------------------------------------------------------------------------
extern "C" void kernel_launch(void* const* d_in, const int* in_sizes, int n_in,
                              void* d_out, int out_size) {
    const int*   concepts = (const int*)d_in[0];
    const int*   lens     = (const int*)d_in[1];
    const float* emb      = (const float*)d_in[2];
    const float* Wih_f    = (const float*)d_in[3];
    const float* Whh_f    = (const float*)d_in[4];
    const float* b_f      = (const float*)d_in[5];
    const float* Wih_b    = (const float*)d_in[6];
    const float* Whh_b    = (const float*)d_in[7];
    const float* b_b      = (const float*)d_in[8];
    const float* Ua       = (const float*)d_in[9];
    const float* Wa       = (const float*)d_in[10];
    const float* va       = (const float*)d_in[11];
    float* out = (float*)d_out;

    k_gather<<<S_ * B_, 64>>>(concepts, emb);
    k_xgemm<<<dim3(64, 8, 2), 256>>>(Wih_f, b_f, Wih_b, b_b);
    k_zero_bar<<<1, 256>>>();
    k_steps<<<2 * NCTA_DIR, 512>>>(lens, Whh_f, Whh_b);
    k_uw<<<dim3(S_, B_), 64>>>(lens, Ua, Wa);
    k_scores<<<dim3(S_, B_), 128>>>(va, out);
}

// round 6
// speedup vs baseline: 1.6605x; 1.0449x over previous
#include <cuda_runtime.h>
#include <math.h>
#include <stdint.h>

typedef unsigned long long ull;

// Problem constants
constexpr int S_   = 128;   // sequence length
constexpr int B_   = 64;    // batch
constexpr int E_   = 256;   // embedding dim
constexpr int H_   = 256;   // hidden
constexpr int G4_  = 1024;  // 4*H (gates)
constexpr int HID_ = 30;    // attention hidden
constexpr int NCTA_DIR = 64;   // CTAs per direction in persistent step kernel

// Scratch (static device globals — no runtime allocation)
__device__ float g_emb[S_ * B_ * E_];        // (t,b,e)
__device__ float g_X[2 * S_ * B_ * G4_];     // x-projections per dir, bias folded in
__device__ float g_h[2 * S_ * B_ * H_];      // [dir][t][b][k]  (for K4)
__device__ float g_hT[2][2][H_][B_];         // ping-pong [dir][parity][k][b]
__device__ int   g_bar[2 * S_];              // grid-barrier arrival counters
__device__ float g_U[B_ * S_ * HID_];        // u = enc @ Ua^T
__device__ float g_Wt[B_ * HID_ * S_];       // w transposed: [b][k][s]

// fast activations: MUFU-based, rel err ~2e-7 (budget is 1e-3)
__device__ __forceinline__ float fsig(float x)  { return 1.0f / (1.0f + __expf(-x)); }
__device__ __forceinline__ float ftanh(float x) { return 2.0f / (1.0f + __expf(-2.0f * x)) - 1.0f; }

// pure (non-volatile) packed fp32 math — scheduler may move these freely
__device__ __forceinline__ void ffma2(ull& d, ull a, ull b) {
    asm("fma.rn.f32x2 %0, %1, %2, %0;" : "+l"(d) : "l"(a), "l"(b));
}
__device__ __forceinline__ ull pack2(float lo, float hi) {
    ull r; asm("mov.b64 %0, {%1, %2};" : "=l"(r) : "f"(lo), "f"(hi)); return r;
}
__device__ __forceinline__ float2 unpack2(ull v) {
    float2 r; asm("mov.b64 {%0, %1}, %2;" : "=f"(r.x), "=f"(r.y) : "l"(v)); return r;
}
// L1-bypassing 16B load (h produced by other CTAs within this launch)
__device__ __forceinline__ void ldcg128(ull& x, ull& y, const float* p) {
    asm volatile("ld.global.cg.v2.u64 {%0, %1}, [%2];" : "=l"(x), "=l"(y) : "l"(p));
}
__device__ __forceinline__ void stcg32(float* p, float v) {
    asm volatile("st.global.cg.f32 [%0], %1;" :: "l"(p), "f"(v));
}

// ---------------------------------------------------------------------------
// K0: zero the grid-barrier counters (stream-ordered before k_steps)
// ---------------------------------------------------------------------------
__global__ void k_zero_bar() {
    if (threadIdx.x < 2 * S_) g_bar[threadIdx.x] = 0;
}

// ---------------------------------------------------------------------------
// K1: embedding gather.  grid = S*B blocks, 64 threads (float4 row copy)
// ---------------------------------------------------------------------------
__global__ void k_gather(const int* __restrict__ concepts,
                         const float* __restrict__ table) {
    int tb  = blockIdx.x;                      // t*B + b
    int tok = concepts[tb];
    const float4* src = reinterpret_cast<const float4*>(table + (size_t)tok * E_);
    float4*       dst = reinterpret_cast<float4*>(g_emb + (size_t)tb * E_);
    dst[threadIdx.x] = src[threadIdx.x];
}

// ---------------------------------------------------------------------------
// K2: x-projection GEMM  X[dir] = emb @ Wih[dir]^T + b[dir]
//     M=8192, N=1024, K=256.  BM=BN=128, BK=16, 256 thr, 8x8 microtile,
//     packed f32x2 FMA in the inner product.
// ---------------------------------------------------------------------------
__global__ __launch_bounds__(256) void k_xgemm(const float* __restrict__ Wih_f,
                                               const float* __restrict__ b_f,
                                               const float* __restrict__ Wih_b,
                                               const float* __restrict__ b_b) {
    const int dir = blockIdx.z;
    const float* __restrict__ Wih  = dir ? Wih_b : Wih_f;
    const float* __restrict__ bias = dir ? b_b   : b_f;
    float* __restrict__ Xout = g_X + (size_t)dir * S_ * B_ * G4_;

    __shared__ float As[16][132];   // [k][m] k-major
    __shared__ float Bs[16][132];   // [k][n]

    const int m0  = blockIdx.x * 128;
    const int n0  = blockIdx.y * 128;
    const int tid = threadIdx.x;
    const int tx  = tid & 15;       // -> n
    const int ty  = tid >> 4;       // -> m

    ull acc2[8][4];
#pragma unroll
    for (int i = 0; i < 8; i++)
#pragma unroll
        for (int j = 0; j < 4; j++) acc2[i][j] = 0ull;

    for (int kc = 0; kc < E_; kc += 16) {
#pragma unroll
        for (int p = 0; p < 2; p++) {
            int q  = tid + p * 256;        // 0..511 quads
            int r  = q >> 2;               // row 0..127
            int kq = (q & 3) * 4;          // k quad
            float4 va = *reinterpret_cast<const float4*>(g_emb + (size_t)(m0 + r) * E_ + kc + kq);
            As[kq + 0][r] = va.x; As[kq + 1][r] = va.y;
            As[kq + 2][r] = va.z; As[kq + 3][r] = va.w;
            float4 vb = *reinterpret_cast<const float4*>(Wih + (size_t)(n0 + r) * E_ + kc + kq);
            Bs[kq + 0][r] = vb.x; Bs[kq + 1][r] = vb.y;
            Bs[kq + 2][r] = vb.z; Bs[kq + 3][r] = vb.w;
        }
        __syncthreads();
#pragma unroll
        for (int k = 0; k < 16; k++) {
            float4 a0 = *reinterpret_cast<const float4*>(&As[k][ty * 8]);
            float4 a1 = *reinterpret_cast<const float4*>(&As[k][ty * 8 + 4]);
            ulonglong2 bb0 = *reinterpret_cast<const ulonglong2*>(&Bs[k][tx * 8]);
            ulonglong2 bb1 = *reinterpret_cast<const ulonglong2*>(&Bs[k][tx * 8 + 4]);
            ull b2[4] = { bb0.x, bb0.y, bb1.x, bb1.y };
            float av[8] = { a0.x, a0.y, a0.z, a0.w, a1.x, a1.y, a1.z, a1.w };
#pragma unroll
            for (int i = 0; i < 8; i++) {
                ull ap = pack2(av[i], av[i]);
#pragma unroll
                for (int j = 0; j < 4; j++) ffma2(acc2[i][j], ap, b2[j]);
            }
        }
        __syncthreads();
    }

    // epilogue: add bias, contiguous float4 stores
    float bv[8];
#pragma unroll
    for (int j = 0; j < 8; j++) bv[j] = bias[n0 + tx * 8 + j];
#pragma unroll
    for (int i = 0; i < 8; i++) {
        int m = m0 + ty * 8 + i;
        float2 e0 = unpack2(acc2[i][0]);
        float2 e1 = unpack2(acc2[i][1]);
        float2 e2 = unpack2(acc2[i][2]);
        float2 e3 = unpack2(acc2[i][3]);
        float4 o0, o1;
        o0.x = e0.x + bv[0]; o0.y = e0.y + bv[1];
        o0.z = e1.x + bv[2]; o0.w = e1.y + bv[3];
        o1.x = e2.x + bv[4]; o1.y = e2.y + bv[5];
        o1.z = e3.x + bv[6]; o1.w = e3.y + bv[7];
        float* dst = Xout + (size_t)m * G4_ + n0 + tx * 8;
        *reinterpret_cast<float4*>(dst)     = o0;
        *reinterpret_cast<float4*>(dst + 4) = o1;
    }
}

// ---------------------------------------------------------------------------
// K3: persistent BiLSTM recurrence.  Grid = 128 CTAs (64 per dir), 512 thr.
//     CTA (dir, cb) owns channels [cb*4, cb*4+4) => 16 gate rows.
//     Per-step chain shortened:
//       - X(t+1) prefetch issued BETWEEN barrier arrive and wait, so DRAM
//         latency overlaps detection AND X line-fetches never sit ahead of
//         the h loads in the L1tex queue at step start.
//       - MUFU-based sigmoid/tanh (no software polynomial on the chain).
//     GEMM decomposition: (ks 0..7) x (rq 0..3) x (bq 0..15); per thread
//     4 rows x 4 batches over 32 k; 8 independent f32x2 chains.
// ---------------------------------------------------------------------------
__global__ __launch_bounds__(512, 1) void k_steps(const int* __restrict__ lens,
                                                  const float* __restrict__ Whh_f,
                                                  const float* __restrict__ Whh_b) {
    __shared__ float w_s[256][16];        // [k][row]  16 KB (transposed Whh slice)
    __shared__ float part_s[8][16][64];   // k-slice partial gates  32 KB

    const int tid = threadIdx.x;
    const int dir = blockIdx.x >> 6;
    const int cb  = blockIdx.x & 63;
    const int j0  = cb * 4;
    const float* __restrict__ Whh = dir ? Whh_b : Whh_f;
    const float* __restrict__ X   = g_X + (size_t)dir * S_ * B_ * G4_;

    // load this CTA's 16 Whh rows TRANSPOSED into w_s[k][row]
    {
        int row = tid >> 5;                 // 0..15 (= gate*4 + ch)
        int gg  = row >> 2, ch = row & 3;
        int grw = gg * H_ + j0 + ch;
        const float* src = Whh + (size_t)grw * H_ + (tid & 31) * 8;
#pragma unroll
        for (int u = 0; u < 8; u += 4) {
            float4 v = *reinterpret_cast<const float4*>(src + u);
            int k0 = (tid & 31) * 8 + u;
            w_s[k0 + 0][row] = v.x;
            w_s[k0 + 1][row] = v.y;
            w_s[k0 + 2][row] = v.z;
            w_s[k0 + 3][row] = v.w;
        }
    }

    // GEMM-side ids: 512 = ks(8) x rq(4) x bq(16)
    const int ks = tid >> 6;           // k-slice 0..7 (32 k each)
    const int rq = (tid >> 4) & 3;     // row quad 0..3
    const int bq = tid & 15;           // batch quad 0..15
    const int r0 = rq * 4;
    const int b0 = bq * 4;
    const int kbase = ks * 32;

    // pointwise-side ids (threads < 256: thread = (pch, pb))
    const bool pw  = (tid < 256);
    const int  pch = tid >> 6;         // 0..3 channel within CTA (valid when pw)
    const int  pb  = tid & 63;         // batch
    const int  Lp  = pw ? __ldg(lens + pb) : 0;
    float creg = 0.0f;

    float* __restrict__ houtB = g_h + (size_t)dir * S_ * B_ * H_;
    int* barp = g_bar + dir * S_;

    // X(0) prefetch (before first GEMM; no h loads compete yet)
    float xg0 = 0.f, xg1 = 0.f, xg2 = 0.f, xg3 = 0.f;
    if (pw) {
        int m;
        if (dir == 0) m = pb;
        else { int rr = (0 < Lp) ? (Lp - 1) : 0; m = rr * B_ + pb; }
        const float* Xm = X + (size_t)m * G4_ + j0 + pch;
        xg0 = Xm[0 * H_]; xg1 = Xm[1 * H_]; xg2 = Xm[2 * H_]; xg3 = Xm[3 * H_];
    }
    __syncthreads();   // w_s ready

    for (int t = 0; t < S_; ++t) {
        if (t > 0) {
            ull a00 = 0, a01 = 0, a10 = 0, a11 = 0, a20 = 0, a21 = 0, a30 = 0, a31 = 0;
            const float* hsrc = &g_hT[dir][(t - 1) & 1][0][0] + (size_t)kbase * 64 + b0;
#pragma unroll 8
            for (int kk = 0; kk < 32; ++kk) {
                ull hx, hy;
                ldcg128(hx, hy, hsrc + kk * 64);
                float4 wv = *reinterpret_cast<const float4*>(&w_s[kbase + kk][r0]);
                ull w0 = pack2(wv.x, wv.x), w1 = pack2(wv.y, wv.y);
                ull w2 = pack2(wv.z, wv.z), w3 = pack2(wv.w, wv.w);
                ffma2(a00, w0, hx); ffma2(a01, w0, hy);
                ffma2(a10, w1, hx); ffma2(a11, w1, hy);
                ffma2(a20, w2, hx); ffma2(a21, w2, hy);
                ffma2(a30, w3, hx); ffma2(a31, w3, hy);
            }
            // write 4x4 partial tile
            float2 l0 = unpack2(a00), h0 = unpack2(a01);
            float2 l1 = unpack2(a10), h1 = unpack2(a11);
            float2 l2 = unpack2(a20), h2 = unpack2(a21);
            float2 l3 = unpack2(a30), h3 = unpack2(a31);
            *reinterpret_cast<float4*>(&part_s[ks][r0 + 0][b0]) = make_float4(l0.x, l0.y, h0.x, h0.y);
            *reinterpret_cast<float4*>(&part_s[ks][r0 + 1][b0]) = make_float4(l1.x, l1.y, h1.x, h1.y);
            *reinterpret_cast<float4*>(&part_s[ks][r0 + 2][b0]) = make_float4(l2.x, l2.y, h2.x, h2.y);
            *reinterpret_cast<float4*>(&part_s[ks][r0 + 3][b0]) = make_float4(l3.x, l3.y, h3.x, h3.y);
            __syncthreads();
        }

        // gates + pointwise for (pch, pb) — consumes xg regs (X(t))
        if (pw) {
            float gv0 = xg0, gv1 = xg1, gv2 = xg2, gv3 = xg3;
            if (t > 0) {
#pragma unroll
                for (int s = 0; s < 8; ++s) {
                    gv0 += part_s[s][0 * 4 + pch][pb];
                    gv1 += part_s[s][1 * 4 + pch][pb];
                    gv2 += part_s[s][2 * 4 + pch][pb];
                    gv3 += part_s[s][3 * 4 + pch][pb];
                }
            }
            float cn = fsig(gv1) * creg + fsig(gv0) * ftanh(gv2);
            float hn = fsig(gv3) * ftanh(cn);
            creg = cn;
            houtB[(size_t)t * B_ * H_ + pb * H_ + j0 + pch] = hn;
            stcg32(&g_hT[dir][t & 1][j0 + pch][pb], hn);
        }

        if (t < S_ - 1) {
            __syncthreads();                 // h(t) stores issued CTA-wide
            // arrive FIRST (release orders the h stores)
            if (tid == 0)
                asm volatile("red.release.gpu.global.add.s32 [%0], 1;" :: "l"(barp + t) : "memory");

            // X(t+1) prefetch — overlaps barrier detection; lands behind
            // nothing (no h loads in flight at this point)
            if (pw) {
                int tn = t + 1;
                int m;
                if (dir == 0) m = tn * B_ + pb;
                else { int rr = (tn < Lp) ? (Lp - 1 - tn) : tn; m = rr * B_ + pb; }
                const float* Xm = X + (size_t)m * G4_ + j0 + pch;
                xg0 = Xm[0 * H_]; xg1 = Xm[1 * H_]; xg2 = Xm[2 * H_]; xg3 = Xm[3 * H_];
            }

            // now wait
            if (tid == 0) {
                int guard = 1 << 20;
                int v;
                do {
                    asm volatile("ld.acquire.gpu.global.s32 %0, [%1];" : "=r"(v) : "l"(barp + t) : "memory");
                } while (v < NCTA_DIR && --guard);
            }
            __syncthreads();
        }
    }
}

// ---------------------------------------------------------------------------
// K4: u/w projections.  One block per (b,s); enc row assembled on the fly.
// ---------------------------------------------------------------------------
__global__ void k_uw(const int* __restrict__ lens,
                     const float* __restrict__ Ua,
                     const float* __restrict__ Wa) {
    const int s = blockIdx.x;
    const int b = blockIdx.y;
    __shared__ float enc_s[2 * H_];

    const int L = lens[b];
    const bool valid = (s < L);
    const int ridx = valid ? (L - 1 - s) : s;
    const int tid = threadIdx.x;   // 64

    float4 f4 = make_float4(0.f, 0.f, 0.f, 0.f);
    float4 b4 = make_float4(0.f, 0.f, 0.f, 0.f);
    if (valid) {
        f4 = *reinterpret_cast<const float4*>(g_h + (size_t)s * B_ * H_ + b * H_ + tid * 4);
        b4 = *reinterpret_cast<const float4*>(g_h + (size_t)S_ * B_ * H_ +
                                              (size_t)ridx * B_ * H_ + b * H_ + tid * 4);
    }
    *reinterpret_cast<float4*>(&enc_s[tid * 4])       = f4;
    *reinterpret_cast<float4*>(&enc_s[H_ + tid * 4])  = b4;
    __syncthreads();

    if (tid < 2 * HID_) {
        const float* __restrict__ Wrow =
            (tid < HID_) ? (Ua + (size_t)tid * 2 * H_) : (Wa + (size_t)(tid - HID_) * 2 * H_);
        float acc = 0.f;
#pragma unroll 4
        for (int k = 0; k < 2 * H_; k += 4) {
            float4 wv = *reinterpret_cast<const float4*>(Wrow + k);
            float4 ev = *reinterpret_cast<const float4*>(&enc_s[k]);
            acc += wv.x * ev.x + wv.y * ev.y + wv.z * ev.z + wv.w * ev.w;
        }
        if (tid < HID_)
            g_U[((size_t)b * S_ + s) * HID_ + tid] = acc;
        else
            g_Wt[(size_t)b * HID_ * S_ + (size_t)(tid - HID_) * S_ + s] = acc;
    }
}

// ---------------------------------------------------------------------------
// K5: scores + predictions (MUFU tanh).
// ---------------------------------------------------------------------------
__global__ void k_scores(const float* __restrict__ va, float* __restrict__ out) {
    const int i = blockIdx.x;
    const int b = blockIdx.y;
    const int j = threadIdx.x;   // 128

    __shared__ float u_s[HID_];
    __shared__ float va_s[HID_];
    if (j < HID_) {
        u_s[j]  = g_U[((size_t)b * S_ + i) * HID_ + j];
        va_s[j] = va[j];
    }
    __syncthreads();

    const float* __restrict__ Wb = g_Wt + (size_t)b * HID_ * S_;
    float acc = 0.f;
#pragma unroll
    for (int k = 0; k < HID_; k++) {
        float wv = Wb[k * S_ + j];
        acc += ftanh(u_s[k] + wv) * va_s[k];
    }
    size_t idx = ((size_t)b * S_ + i) * S_ + j;
    out[idx] = acc;
    out[(size_t)B_ * S_ * S_ + idx] = (acc >= 0.0f) ? 1.0f : 0.0f;
}

// ---------------------------------------------------------------------------
extern "C" void kernel_launch(void* const* d_in, const int* in_sizes, int n_in,
                              void* d_out, int out_size) {
    const int*   concepts = (const int*)d_in[0];
    const int*   lens     = (const int*)d_in[1];
    const float* emb      = (const float*)d_in[2];
    const float* Wih_f    = (const float*)d_in[3];
    const float* Whh_f    = (const float*)d_in[4];
    const float* b_f      = (const float*)d_in[5];
    const float* Wih_b    = (const float*)d_in[6];
    const float* Whh_b    = (const float*)d_in[7];
    const float* b_b      = (const float*)d_in[8];
    const float* Ua       = (const float*)d_in[9];
    const float* Wa       = (const float*)d_in[10];
    const float* va       = (const float*)d_in[11];
    float* out = (float*)d_out;

    k_gather<<<S_ * B_, 64>>>(concepts, emb);
    k_xgemm<<<dim3(64, 8, 2), 256>>>(Wih_f, b_f, Wih_b, b_b);
    k_zero_bar<<<1, 256>>>();
    k_steps<<<2 * NCTA_DIR, 512>>>(lens, Whh_f, Whh_b);
    k_uw<<<dim3(S_, B_), 64>>>(lens, Ua, Wa);
    k_scores<<<dim3(S_, B_), 128>>>(va, out);
}

// round 7
// speedup vs baseline: 1.9924x; 1.1999x over previous
#include <cuda_runtime.h>
#include <math.h>
#include <stdint.h>

typedef unsigned long long ull;

// Problem constants
constexpr int S_   = 128;   // sequence length
constexpr int B_   = 64;    // batch
constexpr int E_   = 256;   // embedding dim
constexpr int H_   = 256;   // hidden
constexpr int G4_  = 1024;  // 4*H (gates)
constexpr int HID_ = 30;    // attention hidden
constexpr int NCTA_DIR = 64;   // CTAs per direction in persistent step kernel

// Scratch (static device globals — no runtime allocation)
__device__ float g_emb[S_ * B_ * E_];        // (t,b,e)
__device__ float g_embT[E_ * S_ * B_];       // transposed: [e][t*B+b]
__device__ float g_WihT[2 * E_ * G4_];       // transposed Wih per dir: [k][n]
__device__ float g_X[2 * S_ * B_ * G4_];     // x-projections per dir, bias folded in
__device__ float g_h[2 * S_ * B_ * H_];      // [dir][t][b][k]  (for K4)
__device__ float g_hT[2][2][H_][B_];         // ping-pong [dir][parity][k][b]
__device__ int   g_bar[2 * S_];              // grid-barrier arrival counters
__device__ float g_U[B_ * S_ * HID_];        // u = enc @ Ua^T
__device__ float g_Wt[B_ * HID_ * S_];       // w transposed: [b][k][s]

// fast activations: MUFU-based, rel err ~2e-7 (budget is 1e-3)
__device__ __forceinline__ float fsig(float x)  { return 1.0f / (1.0f + __expf(-x)); }
__device__ __forceinline__ float ftanh(float x) { return 2.0f / (1.0f + __expf(-2.0f * x)) - 1.0f; }

// pure (non-volatile) packed fp32 math — scheduler may move these freely
__device__ __forceinline__ void ffma2(ull& d, ull a, ull b) {
    asm("fma.rn.f32x2 %0, %1, %2, %0;" : "+l"(d) : "l"(a), "l"(b));
}
__device__ __forceinline__ ull pack2(float lo, float hi) {
    ull r; asm("mov.b64 %0, {%1, %2};" : "=l"(r) : "f"(lo), "f"(hi)); return r;
}
__device__ __forceinline__ float2 unpack2(ull v) {
    float2 r; asm("mov.b64 {%0, %1}, %2;" : "=f"(r.x), "=f"(r.y) : "l"(v)); return r;
}
// L1-bypassing 16B load (h produced by other CTAs within this launch)
__device__ __forceinline__ void ldcg128(ull& x, ull& y, const float* p) {
    asm volatile("ld.global.cg.v2.u64 {%0, %1}, [%2];" : "=l"(x), "=l"(y) : "l"(p));
}
__device__ __forceinline__ void stcg32(float* p, float v) {
    asm volatile("st.global.cg.f32 [%0], %1;" :: "l"(p), "f"(v));
}
__device__ __forceinline__ void cp16(uint32_t smem_dst, const void* gsrc) {
    asm volatile("cp.async.cg.shared.global [%0], [%1], 16;" :: "r"(smem_dst), "l"(gsrc) : "memory");
}

// ---------------------------------------------------------------------------
// K0: zero the grid-barrier counters (stream-ordered before k_steps)
// ---------------------------------------------------------------------------
__global__ void k_zero_bar() {
    if (threadIdx.x < 2 * S_) g_bar[threadIdx.x] = 0;
}

// ---------------------------------------------------------------------------
// K1: embedding gather.  grid = S*B blocks, 64 threads (float4 row copy)
// ---------------------------------------------------------------------------
__global__ void k_gather(const int* __restrict__ concepts,
                         const float* __restrict__ table) {
    int tb  = blockIdx.x;                      // t*B + b
    int tok = concepts[tb];
    const float4* src = reinterpret_cast<const float4*>(table + (size_t)tok * E_);
    float4*       dst = reinterpret_cast<float4*>(g_emb + (size_t)tb * E_);
    dst[threadIdx.x] = src[threadIdx.x];
}

// ---------------------------------------------------------------------------
// K1b: tiled transpose  src[M][N] -> dst[N][M]   (M,N multiples of 32)
// ---------------------------------------------------------------------------
__global__ void k_transpose(const float* __restrict__ src, float* __restrict__ dst,
                            int M, int N) {
    __shared__ float t[32][33];
    int nb = blockIdx.x * 32, mb = blockIdx.y * 32;
    int tx = threadIdx.x, ty = threadIdx.y;   // (32, 8)
#pragma unroll
    for (int i = 0; i < 4; i++)
        t[ty + i * 8][tx] = src[(size_t)(mb + ty + i * 8) * N + nb + tx];
    __syncthreads();
#pragma unroll
    for (int i = 0; i < 4; i++)
        dst[(size_t)(nb + ty + i * 8) * M + mb + tx] = t[tx][ty + i * 8];
}

// ---------------------------------------------------------------------------
// K2: x-projection GEMM  X[dir] = emb @ Wih[dir]^T + b[dir]
//     M=8192, N=1024, K=256.  BM=BN=128, BK=16, 256 thr, 8x8 microtile,
//     packed f32x2 FMA.  Sources pre-transposed (g_embT / g_WihT) so tiles
//     load k-major directly via cp.async; 2-stage double buffer.
// ---------------------------------------------------------------------------
__global__ __launch_bounds__(256) void k_xgemm(const float* __restrict__ b_f,
                                               const float* __restrict__ b_b) {
    const int dir = blockIdx.z;
    const float* __restrict__ AT   = g_embT;                      // [k][8192]
    const float* __restrict__ BT   = g_WihT + (size_t)dir * E_ * G4_;  // [k][1024]
    const float* __restrict__ bias = dir ? b_b : b_f;
    float* __restrict__ Xout = g_X + (size_t)dir * S_ * B_ * G4_;

    __shared__ float As[2][16][132];   // [stage][k][m]
    __shared__ float Bs[2][16][132];   // [stage][k][n]

    const int m0  = blockIdx.x * 128;
    const int n0  = blockIdx.y * 128;
    const int tid = threadIdx.x;
    const int tx  = tid & 15;       // -> n
    const int ty  = tid >> 4;       // -> m

    const uint32_t as_sa = (uint32_t)__cvta_generic_to_shared(&As[0][0][0]);
    const uint32_t bs_sa = (uint32_t)__cvta_generic_to_shared(&Bs[0][0][0]);
    const int q0 = tid * 2;
    const int r0q = q0 >> 5, c0q = (q0 & 31) * 4;        // quad 0: row, col4
    const int r1q = (q0 + 1) >> 5, c1q = ((q0 + 1) & 31) * 4;

    auto load_stage = [&](int st, int kc) {
        uint32_t abase = as_sa + st * (16 * 132 * 4);
        uint32_t bbase = bs_sa + st * (16 * 132 * 4);
        cp16(abase + (r0q * 132 + c0q) * 4, AT + (size_t)(kc + r0q) * 8192 + m0 + c0q);
        cp16(abase + (r1q * 132 + c1q) * 4, AT + (size_t)(kc + r1q) * 8192 + m0 + c1q);
        cp16(bbase + (r0q * 132 + c0q) * 4, BT + (size_t)(kc + r0q) * 1024 + n0 + c0q);
        cp16(bbase + (r1q * 132 + c1q) * 4, BT + (size_t)(kc + r1q) * 1024 + n0 + c1q);
        asm volatile("cp.async.commit_group;" ::: "memory");
    };

    ull acc2[8][4];
#pragma unroll
    for (int i = 0; i < 8; i++)
#pragma unroll
        for (int j = 0; j < 4; j++) acc2[i][j] = 0ull;

    load_stage(0, 0);
#pragma unroll 1
    for (int it = 0; it < 16; ++it) {
        const int cur = it & 1;
        if (it < 15) load_stage(cur ^ 1, (it + 1) * 16);
        if (it < 15) asm volatile("cp.async.wait_group 1;" ::: "memory");
        else         asm volatile("cp.async.wait_group 0;" ::: "memory");
        __syncthreads();
#pragma unroll
        for (int k = 0; k < 16; k++) {
            float4 a0 = *reinterpret_cast<const float4*>(&As[cur][k][ty * 8]);
            float4 a1 = *reinterpret_cast<const float4*>(&As[cur][k][ty * 8 + 4]);
            ulonglong2 bb0 = *reinterpret_cast<const ulonglong2*>(&Bs[cur][k][tx * 8]);
            ulonglong2 bb1 = *reinterpret_cast<const ulonglong2*>(&Bs[cur][k][tx * 8 + 4]);
            ull b2[4] = { bb0.x, bb0.y, bb1.x, bb1.y };
            float av[8] = { a0.x, a0.y, a0.z, a0.w, a1.x, a1.y, a1.z, a1.w };
#pragma unroll
            for (int i = 0; i < 8; i++) {
                ull ap = pack2(av[i], av[i]);
#pragma unroll
                for (int j = 0; j < 4; j++) ffma2(acc2[i][j], ap, b2[j]);
            }
        }
        __syncthreads();
    }

    // epilogue: add bias, contiguous float4 stores
    float bv[8];
#pragma unroll
    for (int j = 0; j < 8; j++) bv[j] = bias[n0 + tx * 8 + j];
#pragma unroll
    for (int i = 0; i < 8; i++) {
        int m = m0 + ty * 8 + i;
        float2 e0 = unpack2(acc2[i][0]);
        float2 e1 = unpack2(acc2[i][1]);
        float2 e2 = unpack2(acc2[i][2]);
        float2 e3 = unpack2(acc2[i][3]);
        float4 o0, o1;
        o0.x = e0.x + bv[0]; o0.y = e0.y + bv[1];
        o0.z = e1.x + bv[2]; o0.w = e1.y + bv[3];
        o1.x = e2.x + bv[4]; o1.y = e2.y + bv[5];
        o1.z = e3.x + bv[6]; o1.w = e3.y + bv[7];
        float* dst = Xout + (size_t)m * G4_ + n0 + tx * 8;
        *reinterpret_cast<float4*>(dst)     = o0;
        *reinterpret_cast<float4*>(dst + 4) = o1;
    }
}

// ---------------------------------------------------------------------------
// K3: persistent BiLSTM recurrence (unchanged from R6 — passing at 516us).
// ---------------------------------------------------------------------------
__global__ __launch_bounds__(512, 1) void k_steps(const int* __restrict__ lens,
                                                  const float* __restrict__ Whh_f,
                                                  const float* __restrict__ Whh_b) {
    __shared__ float w_s[256][16];        // [k][row]  16 KB (transposed Whh slice)
    __shared__ float part_s[8][16][64];   // k-slice partial gates  32 KB

    const int tid = threadIdx.x;
    const int dir = blockIdx.x >> 6;
    const int cb  = blockIdx.x & 63;
    const int j0  = cb * 4;
    const float* __restrict__ Whh = dir ? Whh_b : Whh_f;
    const float* __restrict__ X   = g_X + (size_t)dir * S_ * B_ * G4_;

    {
        int row = tid >> 5;                 // 0..15 (= gate*4 + ch)
        int gg  = row >> 2, ch = row & 3;
        int grw = gg * H_ + j0 + ch;
        const float* src = Whh + (size_t)grw * H_ + (tid & 31) * 8;
#pragma unroll
        for (int u = 0; u < 8; u += 4) {
            float4 v = *reinterpret_cast<const float4*>(src + u);
            int k0 = (tid & 31) * 8 + u;
            w_s[k0 + 0][row] = v.x;
            w_s[k0 + 1][row] = v.y;
            w_s[k0 + 2][row] = v.z;
            w_s[k0 + 3][row] = v.w;
        }
    }

    const int ks = tid >> 6;           // k-slice 0..7 (32 k each)
    const int rq = (tid >> 4) & 3;     // row quad 0..3
    const int bq = tid & 15;           // batch quad 0..15
    const int r0 = rq * 4;
    const int b0 = bq * 4;
    const int kbase = ks * 32;

    const bool pw  = (tid < 256);
    const int  pch = tid >> 6;         // 0..3 channel within CTA (valid when pw)
    const int  pb  = tid & 63;         // batch
    const int  Lp  = pw ? __ldg(lens + pb) : 0;
    float creg = 0.0f;

    float* __restrict__ houtB = g_h + (size_t)dir * S_ * B_ * H_;
    int* barp = g_bar + dir * S_;

    float xg0 = 0.f, xg1 = 0.f, xg2 = 0.f, xg3 = 0.f;
    if (pw) {
        int m;
        if (dir == 0) m = pb;
        else { int rr = (0 < Lp) ? (Lp - 1) : 0; m = rr * B_ + pb; }
        const float* Xm = X + (size_t)m * G4_ + j0 + pch;
        xg0 = Xm[0 * H_]; xg1 = Xm[1 * H_]; xg2 = Xm[2 * H_]; xg3 = Xm[3 * H_];
    }
    __syncthreads();   // w_s ready

    for (int t = 0; t < S_; ++t) {
        if (t > 0) {
            ull a00 = 0, a01 = 0, a10 = 0, a11 = 0, a20 = 0, a21 = 0, a30 = 0, a31 = 0;
            const float* hsrc = &g_hT[dir][(t - 1) & 1][0][0] + (size_t)kbase * 64 + b0;
#pragma unroll 8
            for (int kk = 0; kk < 32; ++kk) {
                ull hx, hy;
                ldcg128(hx, hy, hsrc + kk * 64);
                float4 wv = *reinterpret_cast<const float4*>(&w_s[kbase + kk][r0]);
                ull w0 = pack2(wv.x, wv.x), w1 = pack2(wv.y, wv.y);
                ull w2 = pack2(wv.z, wv.z), w3 = pack2(wv.w, wv.w);
                ffma2(a00, w0, hx); ffma2(a01, w0, hy);
                ffma2(a10, w1, hx); ffma2(a11, w1, hy);
                ffma2(a20, w2, hx); ffma2(a21, w2, hy);
                ffma2(a30, w3, hx); ffma2(a31, w3, hy);
            }
            float2 l0 = unpack2(a00), h0 = unpack2(a01);
            float2 l1 = unpack2(a10), h1 = unpack2(a11);
            float2 l2 = unpack2(a20), h2 = unpack2(a21);
            float2 l3 = unpack2(a30), h3 = unpack2(a31);
            *reinterpret_cast<float4*>(&part_s[ks][r0 + 0][b0]) = make_float4(l0.x, l0.y, h0.x, h0.y);
            *reinterpret_cast<float4*>(&part_s[ks][r0 + 1][b0]) = make_float4(l1.x, l1.y, h1.x, h1.y);
            *reinterpret_cast<float4*>(&part_s[ks][r0 + 2][b0]) = make_float4(l2.x, l2.y, h2.x, h2.y);
            *reinterpret_cast<float4*>(&part_s[ks][r0 + 3][b0]) = make_float4(l3.x, l3.y, h3.x, h3.y);
            __syncthreads();
        }

        if (pw) {
            float gv0 = xg0, gv1 = xg1, gv2 = xg2, gv3 = xg3;
            if (t > 0) {
#pragma unroll
                for (int s = 0; s < 8; ++s) {
                    gv0 += part_s[s][0 * 4 + pch][pb];
                    gv1 += part_s[s][1 * 4 + pch][pb];
                    gv2 += part_s[s][2 * 4 + pch][pb];
                    gv3 += part_s[s][3 * 4 + pch][pb];
                }
            }
            float cn = fsig(gv1) * creg + fsig(gv0) * ftanh(gv2);
            float hn = fsig(gv3) * ftanh(cn);
            creg = cn;
            houtB[(size_t)t * B_ * H_ + pb * H_ + j0 + pch] = hn;
            stcg32(&g_hT[dir][t & 1][j0 + pch][pb], hn);
        }

        if (t < S_ - 1) {
            __syncthreads();                 // h(t) stores issued CTA-wide
            if (tid == 0)
                asm volatile("red.release.gpu.global.add.s32 [%0], 1;" :: "l"(barp + t) : "memory");

            if (pw) {
                int tn = t + 1;
                int m;
                if (dir == 0) m = tn * B_ + pb;
                else { int rr = (tn < Lp) ? (Lp - 1 - tn) : tn; m = rr * B_ + pb; }
                const float* Xm = X + (size_t)m * G4_ + j0 + pch;
                xg0 = Xm[0 * H_]; xg1 = Xm[1 * H_]; xg2 = Xm[2 * H_]; xg3 = Xm[3 * H_];
            }

            if (tid == 0) {
                int guard = 1 << 20;
                int v;
                do {
                    asm volatile("ld.acquire.gpu.global.s32 %0, [%1];" : "=r"(v) : "l"(barp + t) : "memory");
                } while (v < NCTA_DIR && --guard);
            }
            __syncthreads();
        }
    }
}

// ---------------------------------------------------------------------------
// K4: u/w projections.  Block = (b, s-group of 8), 512 threads.
//     enc rows staged in smem; each W row read by 8 threads (L1-shared);
//     L2 traffic ~140 MB total (was ~1 GB with per-(b,s) blocks).
// ---------------------------------------------------------------------------
__global__ __launch_bounds__(512) void k_uw(const int* __restrict__ lens,
                                            const float* __restrict__ Ua,
                                            const float* __restrict__ Wa) {
    __shared__ float enc_s[8][516];

    const int b  = blockIdx.x;
    const int sg = blockIdx.y;
    const int tid = threadIdx.x;
    const int L = lens[b];

    // stage 8 enc rows (each 512 = fwd|bwd), masked by validity
    {
        int lr = tid >> 6;             // local s row 0..7
        int lc = (tid & 63) * 8;       // col 0..504 step 8
        int s_row = sg * 8 + lr;
        bool valid = (s_row < L);
        int ridx = valid ? (L - 1 - s_row) : s_row;
        const float* src = (lc < 256)
            ? g_h + (size_t)s_row * B_ * H_ + b * H_ + lc
            : g_h + (size_t)S_ * B_ * H_ + (size_t)ridx * B_ * H_ + b * H_ + (lc - 256);
        float4 v0 = make_float4(0.f, 0.f, 0.f, 0.f);
        float4 v1 = v0;
        if (valid) {
            v0 = *reinterpret_cast<const float4*>(src);
            v1 = *reinterpret_cast<const float4*>(src + 4);
        }
        *reinterpret_cast<float4*>(&enc_s[lr][lc])     = v0;
        *reinterpret_cast<float4*>(&enc_s[lr][lc + 4]) = v1;
    }
    __syncthreads();

    // compute: thread = (row 0..63, sl 0..7); rows 0..29 -> Ua, 30..59 -> Wa
    const int row = tid >> 3;
    const int sl  = tid & 7;
    if (row < 2 * HID_) {
        const float* __restrict__ Wrow =
            (row < HID_) ? (Ua + (size_t)row * 2 * H_) : (Wa + (size_t)(row - HID_) * 2 * H_);
        float acc = 0.f;
#pragma unroll 8
        for (int k = 0; k < 2 * H_; k += 4) {
            float4 wv = *reinterpret_cast<const float4*>(Wrow + k);
            float4 ev = *reinterpret_cast<const float4*>(&enc_s[sl][k]);
            acc += wv.x * ev.x + wv.y * ev.y + wv.z * ev.z + wv.w * ev.w;
        }
        int s = sg * 8 + sl;
        if (row < HID_)
            g_U[((size_t)b * S_ + s) * HID_ + row] = acc;
        else
            g_Wt[(size_t)b * HID_ * S_ + (size_t)(row - HID_) * S_ + s] = acc;
    }
}

// ---------------------------------------------------------------------------
// K5: scores + predictions (MUFU tanh).
// ---------------------------------------------------------------------------
__global__ void k_scores(const float* __restrict__ va, float* __restrict__ out) {
    const int i = blockIdx.x;
    const int b = blockIdx.y;
    const int j = threadIdx.x;   // 128

    __shared__ float u_s[HID_];
    __shared__ float va_s[HID_];
    if (j < HID_) {
        u_s[j]  = g_U[((size_t)b * S_ + i) * HID_ + j];
        va_s[j] = va[j];
    }
    __syncthreads();

    const float* __restrict__ Wb = g_Wt + (size_t)b * HID_ * S_;
    float acc = 0.f;
#pragma unroll
    for (int k = 0; k < HID_; k++) {
        float wv = Wb[k * S_ + j];
        acc += ftanh(u_s[k] + wv) * va_s[k];
    }
    size_t idx = ((size_t)b * S_ + i) * S_ + j;
    out[idx] = acc;
    out[(size_t)B_ * S_ * S_ + idx] = (acc >= 0.0f) ? 1.0f : 0.0f;
}

// ---------------------------------------------------------------------------
extern "C" void kernel_launch(void* const* d_in, const int* in_sizes, int n_in,
                              void* d_out, int out_size) {
    const int*   concepts = (const int*)d_in[0];
    const int*   lens     = (const int*)d_in[1];
    const float* emb      = (const float*)d_in[2];
    const float* Wih_f    = (const float*)d_in[3];
    const float* Whh_f    = (const float*)d_in[4];
    const float* b_f      = (const float*)d_in[5];
    const float* Wih_b    = (const float*)d_in[6];
    const float* Whh_b    = (const float*)d_in[7];
    const float* b_b      = (const float*)d_in[8];
    const float* Ua       = (const float*)d_in[9];
    const float* Wa       = (const float*)d_in[10];
    const float* va       = (const float*)d_in[11];
    float* out = (float*)d_out;

    float* embT_p = nullptr;
    float* WihT_p = nullptr;
    cudaGetSymbolAddress((void**)&embT_p, g_embT);
    cudaGetSymbolAddress((void**)&WihT_p, g_WihT);
    float* emb_p = nullptr;
    cudaGetSymbolAddress((void**)&emb_p, g_emb);

    k_gather<<<S_ * B_, 64>>>(concepts, emb);
    // transposes: emb (8192x256 -> 256x8192), Wih_f/Wih_b (1024x256 -> 256x1024)
    k_transpose<<<dim3(E_ / 32, (S_ * B_) / 32), dim3(32, 8)>>>(emb_p, embT_p, S_ * B_, E_);
    k_transpose<<<dim3(E_ / 32, G4_ / 32), dim3(32, 8)>>>(Wih_f, WihT_p, G4_, E_);
    k_transpose<<<dim3(E_ / 32, G4_ / 32), dim3(32, 8)>>>(Wih_b, WihT_p + E_ * G4_, G4_, E_);
    k_xgemm<<<dim3(64, 8, 2), 256>>>(b_f, b_b);
    k_zero_bar<<<1, 256>>>();
    k_steps<<<2 * NCTA_DIR, 512>>>(lens, Whh_f, Whh_b);
    k_uw<<<dim3(B_, S_ / 8), 512>>>(lens, Ua, Wa);
    k_scores<<<dim3(S_, B_), 128>>>(va, out);
}